// round 6
// baseline (speedup 1.0000x reference)
#include <cuda_runtime.h>
#include <cstdint>

// ---------------------------------------------------------------------------
// 2-layer GAT (heads=2), CSR-based, tf32 tensor-core GEMMs (3xTF32 precision).
// ---------------------------------------------------------------------------

#define NN 50000
#define NE 800000

__device__ float g_xl1[NN * 128];
__device__ float g_out1[NN * 128];
__device__ float g_xl2[NN * 256];
__device__ float g_asrc[NN * 2];
__device__ float g_adst[NN * 2];
__device__ int   g_cnt[NN];
__device__ int   g_rowptr[NN + 1];
__device__ int   g_off[NN];
__device__ int   g_col[NE];

__device__ __forceinline__ float leaky(float a) { return a > 0.f ? a : 0.2f * a; }

// ---------------------------------------------------------------------------
// TF32 helpers
// ---------------------------------------------------------------------------
__device__ __forceinline__ void tf32_split(float a, float* d) {
    uint32_t h;
    asm("cvt.rna.tf32.f32 %0, %1;" : "=r"(h) : "f"(a));
    float hf = __uint_as_float(h);
    float lo = a - hf;
    uint32_t l;
    asm("cvt.rna.tf32.f32 %0, %1;" : "=r"(l) : "f"(lo));
    d[0] = hf;
    d[1] = __uint_as_float(l);
}

__device__ __forceinline__ void mma8(float* c, const float* a, const float* b) {
    asm volatile(
        "mma.sync.aligned.m16n8k8.row.col.f32.tf32.tf32.f32 "
        "{%0,%1,%2,%3}, {%4,%5,%6,%7}, {%8,%9}, {%0,%1,%2,%3};"
        : "+f"(c[0]), "+f"(c[1]), "+f"(c[2]), "+f"(c[3])
        : "r"(__float_as_uint(a[0])), "r"(__float_as_uint(a[1])),
          "r"(__float_as_uint(a[2])), "r"(__float_as_uint(a[3])),
          "r"(__float_as_uint(b[0])), "r"(__float_as_uint(b[1])));
}

// ---------------------------------------------------------------------------
// TF32 GEMM: C[M,NC] = A[M,KTOT] @ B[KTOT,NC], 3xTF32 for fp32-level accuracy.
// BM=128, BN=128, BK=16, 256 threads (8 warps, 4x2), warp tile 32x64.
// smem stores hi/lo interleaved so a fragment element is one LDS.64.
// ---------------------------------------------------------------------------
template <int KTOT, int NC>
__global__ __launch_bounds__(256)
void gemm_tf32_kernel(const float* __restrict__ A, const float* __restrict__ B,
                      float* __restrict__ C, int M)
{
    constexpr int BM = 128, BN = 128, BK = 16;
    constexpr int SA = BK * 2 + 2;   // 34 floats per A row (hi/lo + pad)
    constexpr int SB = BN * 2 + 4;   // 260 floats per B row

    __shared__ float sA[BM * SA];
    __shared__ float sB[BK * SB];

    const int tid = threadIdx.x;
    const int lane = tid & 31, wid = tid >> 5;
    const int wm = wid >> 1, wn = wid & 1;      // 4 x 2 warp grid
    const int g = lane >> 2, tg = lane & 3;
    const int m0 = blockIdx.x * BM;
    const int nb = blockIdx.y * BN;

    float acc[2][8][4];
#pragma unroll
    for (int mi = 0; mi < 2; mi++)
#pragma unroll
        for (int ni = 0; ni < 8; ni++)
#pragma unroll
            for (int q = 0; q < 4; q++) acc[mi][ni][q] = 0.f;

    for (int k0 = 0; k0 < KTOT; k0 += BK) {
        // load A tile (BM x BK): 512 float4, 2 per thread
#pragma unroll
        for (int i = 0; i < 2; i++) {
            int idx = tid + 256 * i;
            int row = idx >> 2, kq = (idx & 3) * 4;
            float4 v = make_float4(0.f, 0.f, 0.f, 0.f);
            if (m0 + row < M)
                v = *(const float4*)&A[(size_t)(m0 + row) * KTOT + k0 + kq];
            float* d = &sA[row * SA + kq * 2];
            tf32_split(v.x, d); tf32_split(v.y, d + 2);
            tf32_split(v.z, d + 4); tf32_split(v.w, d + 6);
        }
        // load B tile (BK x BN): 512 float4, 2 per thread
#pragma unroll
        for (int i = 0; i < 2; i++) {
            int idx = tid + 256 * i;
            int kr = idx >> 5, nq = (idx & 31) * 4;
            float4 v = *(const float4*)&B[(size_t)(k0 + kr) * NC + nb + nq];
            float* d = &sB[kr * SB + nq * 2];
            tf32_split(v.x, d); tf32_split(v.y, d + 2);
            tf32_split(v.z, d + 4); tf32_split(v.w, d + 6);
        }
        __syncthreads();

#pragma unroll
        for (int ks = 0; ks < BK; ks += 8) {
            float ah[2][4], al[2][4];
#pragma unroll
            for (int mi = 0; mi < 2; mi++) {
                int r = wm * 32 + mi * 16 + g;
                float2 t0 = *(float2*)&sA[r * SA + (ks + tg) * 2];
                float2 t1 = *(float2*)&sA[(r + 8) * SA + (ks + tg) * 2];
                float2 t2 = *(float2*)&sA[r * SA + (ks + tg + 4) * 2];
                float2 t3 = *(float2*)&sA[(r + 8) * SA + (ks + tg + 4) * 2];
                ah[mi][0] = t0.x; al[mi][0] = t0.y;
                ah[mi][1] = t1.x; al[mi][1] = t1.y;
                ah[mi][2] = t2.x; al[mi][2] = t2.y;
                ah[mi][3] = t3.x; al[mi][3] = t3.y;
            }
            float bh[8][2], bl[8][2];
#pragma unroll
            for (int ni = 0; ni < 8; ni++) {
                int c = wn * 64 + ni * 8 + g;
                float2 t0 = *(float2*)&sB[(ks + tg) * SB + c * 2];
                float2 t1 = *(float2*)&sB[(ks + tg + 4) * SB + c * 2];
                bh[ni][0] = t0.x; bl[ni][0] = t0.y;
                bh[ni][1] = t1.x; bl[ni][1] = t1.y;
            }
#pragma unroll
            for (int mi = 0; mi < 2; mi++)
#pragma unroll
                for (int ni = 0; ni < 8; ni++) {
                    mma8(acc[mi][ni], al[mi], bh[ni]);
                    mma8(acc[mi][ni], ah[mi], bl[ni]);
                    mma8(acc[mi][ni], ah[mi], bh[ni]);
                }
        }
        __syncthreads();
    }

    // epilogue
#pragma unroll
    for (int mi = 0; mi < 2; mi++) {
        int r0 = m0 + wm * 32 + mi * 16 + g;
#pragma unroll
        for (int ni = 0; ni < 8; ni++) {
            int c = nb + wn * 64 + ni * 8 + 2 * tg;
            if (r0 < M)
                *(float2*)&C[(size_t)r0 * NC + c] =
                    make_float2(acc[mi][ni][0], acc[mi][ni][1]);
            if (r0 + 8 < M)
                *(float2*)&C[(size_t)(r0 + 8) * NC + c] =
                    make_float2(acc[mi][ni][2], acc[mi][ni][3]);
        }
    }
}

// ---------------------------------------------------------------------------
// Attention coefficients: warp per node.
// ---------------------------------------------------------------------------
template <int F>
__global__ void attn_kernel(const float* __restrict__ xl,
                            const float* __restrict__ att_s,
                            const float* __restrict__ att_d,
                            int n_nodes)
{
    constexpr int FT = 2 * F;
    int w = (blockIdx.x * blockDim.x + threadIdx.x) >> 5;
    int lane = threadIdx.x & 31;
    if (w >= n_nodes) return;

    const float4* row = (const float4*)(xl + (size_t)w * FT);
    const float4* as4 = (const float4*)att_s;
    const float4* ad4 = (const float4*)att_d;

    if constexpr (F == 64) {
        float4 v = row[lane], a = as4[lane], b = ad4[lane];
        float ps = v.x * a.x + v.y * a.y + v.z * a.z + v.w * a.w;
        float pd = v.x * b.x + v.y * b.y + v.z * b.z + v.w * b.w;
#pragma unroll
        for (int o = 8; o > 0; o >>= 1) {
            ps += __shfl_xor_sync(0xffffffffu, ps, o);
            pd += __shfl_xor_sync(0xffffffffu, pd, o);
        }
        if (lane == 0)  { g_asrc[2 * w]     = ps; g_adst[2 * w]     = pd; }
        if (lane == 16) { g_asrc[2 * w + 1] = ps; g_adst[2 * w + 1] = pd; }
    } else {
        float4 v0 = row[lane],      a0 = as4[lane],      b0 = ad4[lane];
        float4 v1 = row[lane + 32], a1 = as4[lane + 32], b1 = ad4[lane + 32];
        float ps0 = v0.x * a0.x + v0.y * a0.y + v0.z * a0.z + v0.w * a0.w;
        float pd0 = v0.x * b0.x + v0.y * b0.y + v0.z * b0.z + v0.w * b0.w;
        float ps1 = v1.x * a1.x + v1.y * a1.y + v1.z * a1.z + v1.w * a1.w;
        float pd1 = v1.x * b1.x + v1.y * b1.y + v1.z * b1.z + v1.w * b1.w;
#pragma unroll
        for (int o = 16; o > 0; o >>= 1) {
            ps0 += __shfl_xor_sync(0xffffffffu, ps0, o);
            pd0 += __shfl_xor_sync(0xffffffffu, pd0, o);
            ps1 += __shfl_xor_sync(0xffffffffu, ps1, o);
            pd1 += __shfl_xor_sync(0xffffffffu, pd1, o);
        }
        if (lane == 0) {
            g_asrc[2 * w] = ps0; g_asrc[2 * w + 1] = ps1;
            g_adst[2 * w] = pd0; g_adst[2 * w + 1] = pd1;
        }
    }
}

// ---------------------------------------------------------------------------
// CSR construction.
// ---------------------------------------------------------------------------
__global__ void zero_cnt_kernel(int n)
{
    int i = blockIdx.x * blockDim.x + threadIdx.x;
    if (i < n) g_cnt[i] = 0;
}

__global__ void hist_kernel(const int* __restrict__ dst, int ne)
{
    int i = blockIdx.x * blockDim.x + threadIdx.x;
    if (i < ne) atomicAdd(&g_cnt[dst[i]], 1);
}

__global__ __launch_bounds__(1024)
void scan_kernel(int n)
{
    __shared__ int s_carry;
    __shared__ int wsum[32];
    int tid = threadIdx.x, lane = tid & 31, wid = tid >> 5;
    if (tid == 0) s_carry = 0;
    __syncthreads();

    for (int base = 0; base < n; base += 4096) {
        int i0 = base + tid * 4;
        int c0 = 0, c1 = 0, c2 = 0, c3 = 0;
        if (i0 + 3 < n) {
            int4 t = *(const int4*)&g_cnt[i0];
            c0 = t.x; c1 = t.y; c2 = t.z; c3 = t.w;
        } else {
            if (i0     < n) c0 = g_cnt[i0];
            if (i0 + 1 < n) c1 = g_cnt[i0 + 1];
            if (i0 + 2 < n) c2 = g_cnt[i0 + 2];
            if (i0 + 3 < n) c3 = g_cnt[i0 + 3];
        }
        int v = c0 + c1 + c2 + c3;
        int s = v;
#pragma unroll
        for (int o = 1; o < 32; o <<= 1) {
            int t = __shfl_up_sync(0xffffffffu, s, o);
            if (lane >= o) s += t;
        }
        if (lane == 31) wsum[wid] = s;
        __syncthreads();
        if (wid == 0) {
            int ws = wsum[lane];
#pragma unroll
            for (int o = 1; o < 32; o <<= 1) {
                int t = __shfl_up_sync(0xffffffffu, ws, o);
                if (lane >= o) ws += t;
            }
            wsum[lane] = ws;
        }
        __syncthreads();
        int excl = s - v + (wid ? wsum[wid - 1] : 0) + s_carry;
        int e0 = excl, e1 = e0 + c0, e2 = e1 + c1, e3 = e2 + c2;
        if (i0     < n) { g_rowptr[i0]     = e0; g_off[i0]     = e0; }
        if (i0 + 1 < n) { g_rowptr[i0 + 1] = e1; g_off[i0 + 1] = e1; }
        if (i0 + 2 < n) { g_rowptr[i0 + 2] = e2; g_off[i0 + 2] = e2; }
        if (i0 + 3 < n) { g_rowptr[i0 + 3] = e3; g_off[i0 + 3] = e3; }
        __syncthreads();
        if (tid == 0) s_carry += wsum[31];
        __syncthreads();
    }
    if (tid == 0) g_rowptr[n] = s_carry;
}

__global__ void scatter_kernel(const int* __restrict__ src, const int* __restrict__ dst, int ne)
{
    int i = blockIdx.x * blockDim.x + threadIdx.x;
    if (i >= ne) return;
    int pos = atomicAdd(&g_off[dst[i]], 1);
    g_col[pos] = src[i];
}

// ---------------------------------------------------------------------------
// Node kernel: warp per destination. Full segment softmax + aggregation.
// ---------------------------------------------------------------------------
template <int F>
__global__ __launch_bounds__(256)
void node_kernel(const float* __restrict__ xl, const float* __restrict__ bias,
                 float* __restrict__ out, int n_nodes)
{
    constexpr int FT = 2 * F;
    int w = (blockIdx.x * blockDim.x + threadIdx.x) >> 5;
    int lane = threadIdx.x & 31;
    if (w >= n_nodes) return;

    const int beg = g_rowptr[w], end = g_rowptr[w + 1];
    const float ad0 = g_adst[2 * w], ad1 = g_adst[2 * w + 1];
    const float as0 = g_asrc[2 * w], as1 = g_asrc[2 * w + 1];
    const float aself0 = leaky(as0 + ad0), aself1 = leaky(as1 + ad1);

    float m0 = aself0, m1 = aself1;
    for (int i = beg + lane; i < end; i += 32) {
        int s = g_col[i];
        m0 = fmaxf(m0, leaky(g_asrc[2 * s]     + ad0));
        m1 = fmaxf(m1, leaky(g_asrc[2 * s + 1] + ad1));
    }
#pragma unroll
    for (int o = 16; o > 0; o >>= 1) {
        m0 = fmaxf(m0, __shfl_xor_sync(0xffffffffu, m0, o));
        m1 = fmaxf(m1, __shfl_xor_sync(0xffffffffu, m1, o));
    }

    float e0 = __expf(aself0 - m0), e1 = __expf(aself1 - m1);
    float den0 = e0, den1 = e1;
    const float4* xrow = (const float4*)(xl + (size_t)w * FT);
    const float4* b4 = (const float4*)bias;
    float4* orow = (float4*)(out + (size_t)w * FT);

    if constexpr (F == 64) {
        const bool h0 = (lane < 16);
        float esel = h0 ? e0 : e1;
        float4 v = xrow[lane];
        float4 acc = make_float4(v.x * esel, v.y * esel, v.z * esel, v.w * esel);
#pragma unroll 2
        for (int i = beg; i < end; i++) {
            int s = g_col[i];
            float f0 = __expf(leaky(g_asrc[2 * s]     + ad0) - m0);
            float f1 = __expf(leaky(g_asrc[2 * s + 1] + ad1) - m1);
            den0 += f0; den1 += f1;
            float fe = h0 ? f0 : f1;
            float4 u = ((const float4*)(xl + (size_t)s * FT))[lane];
            acc.x += u.x * fe; acc.y += u.y * fe;
            acc.z += u.z * fe; acc.w += u.w * fe;
        }
        float id = 1.f / (h0 ? den0 : den1);
        float4 bb = b4[lane];
        orow[lane] = make_float4(acc.x * id + bb.x, acc.y * id + bb.y,
                                 acc.z * id + bb.z, acc.w * id + bb.w);
    } else {
        float4 v0 = xrow[lane], v1 = xrow[lane + 32];
        float4 a0 = make_float4(v0.x * e0, v0.y * e0, v0.z * e0, v0.w * e0);
        float4 a1 = make_float4(v1.x * e1, v1.y * e1, v1.z * e1, v1.w * e1);
#pragma unroll 2
        for (int i = beg; i < end; i++) {
            int s = g_col[i];
            float f0 = __expf(leaky(g_asrc[2 * s]     + ad0) - m0);
            float f1 = __expf(leaky(g_asrc[2 * s + 1] + ad1) - m1);
            den0 += f0; den1 += f1;
            const float4* xs = (const float4*)(xl + (size_t)s * FT);
            float4 u0 = xs[lane], u1 = xs[lane + 32];
            a0.x += u0.x * f0; a0.y += u0.y * f0; a0.z += u0.z * f0; a0.w += u0.w * f0;
            a1.x += u1.x * f1; a1.y += u1.y * f1; a1.z += u1.z * f1; a1.w += u1.w * f1;
        }
        float id0 = 1.f / den0, id1 = 1.f / den1;
        float4 b0 = b4[lane], b1 = b4[lane + 32];
        orow[lane]      = make_float4(a0.x * id0 + b0.x, a0.y * id0 + b0.y,
                                      a0.z * id0 + b0.z, a0.w * id0 + b0.w);
        orow[lane + 32] = make_float4(a1.x * id1 + b1.x, a1.y * id1 + b1.y,
                                      a1.z * id1 + b1.z, a1.w * id1 + b1.w);
    }
}

// ---------------------------------------------------------------------------

extern "C" void kernel_launch(void* const* d_in, const int* in_sizes, int n_in,
                              void* d_out, int out_size)
{
    const float* x   = (const float*)d_in[0];
    const int*   und = (const int*)d_in[1];
    const int*   dir = (const int*)d_in[2];
    const float* W1  = (const float*)d_in[3];
    const float* as1 = (const float*)d_in[4];
    const float* ad1 = (const float*)d_in[5];
    const float* b1  = (const float*)d_in[6];
    const float* W2  = (const float*)d_in[7];
    const float* as2 = (const float*)d_in[8];
    const float* ad2 = (const float*)d_in[9];
    const float* b2  = (const float*)d_in[10];
    float* out = (float*)d_out;

    const int n  = in_sizes[0] / 64;   // 50000
    const int e1 = in_sizes[1] / 2;    // 800000
    const int e2 = in_sizes[2] / 2;    // 800000

    float *xl1p, *out1p, *xl2p;
    cudaGetSymbolAddress((void**)&xl1p,  g_xl1);
    cudaGetSymbolAddress((void**)&out1p, g_out1);
    cudaGetSymbolAddress((void**)&xl2p,  g_xl2);

    const int T = 256;
    auto cdiv = [](long long a, long long b) { return (int)((a + b - 1) / b); };

    // ---------------- Layer 1 (F=64, FT=128) ----------------
    {
        dim3 grid(cdiv(n, 128), 1);
        gemm_tf32_kernel<64, 128><<<grid, 256>>>(x, W1, xl1p, n);
    }
    attn_kernel<64><<<cdiv((long long)n * 32, T), T>>>(xl1p, as1, ad1, n);
    zero_cnt_kernel<<<cdiv(n, T), T>>>(n);
    hist_kernel<<<cdiv(e1, T), T>>>(und + e1, e1);
    scan_kernel<<<1, 1024>>>(n);
    scatter_kernel<<<cdiv(e1, T), T>>>(und, und + e1, e1);
    node_kernel<64><<<cdiv((long long)n * 32, T), T>>>(xl1p, b1, out1p, n);

    // ---------------- Layer 2 (F=128, FT=256) ----------------
    {
        dim3 grid(cdiv(n, 128), 2);
        gemm_tf32_kernel<128, 256><<<grid, 256>>>(out1p, W2, xl2p, n);
    }
    attn_kernel<128><<<cdiv((long long)n * 32, T), T>>>(xl2p, as2, ad2, n);
    zero_cnt_kernel<<<cdiv(n, T), T>>>(n);
    hist_kernel<<<cdiv(e2, T), T>>>(dir + e2, e2);
    scan_kernel<<<1, 1024>>>(n);
    scatter_kernel<<<cdiv(e2, T), T>>>(dir, dir + e2, e2);
    node_kernel<128><<<cdiv((long long)n * 32, T), T>>>(xl2p, b2, out, n);
}

// round 7
// speedup vs baseline: 1.1915x; 1.1915x over previous
#include <cuda_runtime.h>
#include <cstdint>

// ---------------------------------------------------------------------------
// 2-layer GAT (heads=2), CSR-based, SIMT GEMM, chunked node softmax-aggregate.
// ---------------------------------------------------------------------------

#define NN 50000
#define NE 800000

__device__ float g_xl1[NN * 128];
__device__ float g_out1[NN * 128];
__device__ float g_xl2[NN * 256];
__device__ float g_asrc[NN * 2];
__device__ float g_adst[NN * 2];
__device__ int   g_cnt[NN];
__device__ int   g_rowptr[NN + 1];
__device__ int   g_off[NN];
__device__ int   g_col[NE];
__device__ int   g_bsum[32];
__device__ int   g_bsum_scan[32];

__device__ __forceinline__ float leaky(float a) { return a > 0.f ? a : 0.2f * a; }

// ---------------------------------------------------------------------------
// GEMM: C[M,NC] = A[M,KTOT] @ B[KTOT,NC].  TILE_M=64, BK=32, 256 threads.
// ---------------------------------------------------------------------------
template <int KTOT, int NC>
__global__ __launch_bounds__(256)
void gemm_kernel(const float* __restrict__ A, const float* __restrict__ B,
                 float* __restrict__ C, int M)
{
    constexpr int TM = 64, BK = 32;
    constexpr int RM = 8;
    constexpr int RN = NC / 32;

    __shared__ float sA[BK][TM + 1];
    __shared__ float sB[BK][NC];

    const int tid = threadIdx.x;
    const int tx = tid & 31, ty = tid >> 5;
    const int m0 = blockIdx.x * TM;

    float acc[RM][RN];
#pragma unroll
    for (int i = 0; i < RM; i++)
#pragma unroll
        for (int j = 0; j < RN; j++) acc[i][j] = 0.f;

    for (int k0 = 0; k0 < KTOT; k0 += BK) {
#pragma unroll
        for (int i = 0; i < (TM * BK) / 256; i++) {
            int idx = tid + 256 * i;
            int r = idx >> 5;
            int kk = idx & 31;
            int row = m0 + r;
            sA[kk][r] = (row < M) ? A[(size_t)row * KTOT + k0 + kk] : 0.f;
        }
#pragma unroll
        for (int i = 0; i < (BK * NC) / 256; i++) {
            int idx = tid + 256 * i;
            int kk = idx / NC;
            int c  = idx % NC;
            sB[kk][c] = B[(size_t)(k0 + kk) * NC + c];
        }
        __syncthreads();

#pragma unroll 4
        for (int kk = 0; kk < BK; kk++) {
            float xv[RM], wv[RN];
#pragma unroll
            for (int i = 0; i < RM; i++) xv[i] = sA[kk][ty * RM + i];
#pragma unroll
            for (int j = 0; j < RN; j++) wv[j] = sB[kk][tx + 32 * j];
#pragma unroll
            for (int i = 0; i < RM; i++)
#pragma unroll
                for (int j = 0; j < RN; j++) acc[i][j] += xv[i] * wv[j];
        }
        __syncthreads();
    }

#pragma unroll
    for (int i = 0; i < RM; i++) {
        int row = m0 + ty * RM + i;
        if (row < M) {
#pragma unroll
            for (int j = 0; j < RN; j++)
                C[(size_t)row * NC + tx + 32 * j] = acc[i][j];
        }
    }
}

// ---------------------------------------------------------------------------
// Attention coefficients: warp per node.
// ---------------------------------------------------------------------------
template <int F>
__global__ void attn_kernel(const float* __restrict__ xl,
                            const float* __restrict__ att_s,
                            const float* __restrict__ att_d,
                            int n_nodes)
{
    constexpr int FT = 2 * F;
    int w = (blockIdx.x * blockDim.x + threadIdx.x) >> 5;
    int lane = threadIdx.x & 31;
    if (w >= n_nodes) return;

    const float4* row = (const float4*)(xl + (size_t)w * FT);
    const float4* as4 = (const float4*)att_s;
    const float4* ad4 = (const float4*)att_d;

    if constexpr (F == 64) {
        float4 v = row[lane], a = as4[lane], b = ad4[lane];
        float ps = v.x * a.x + v.y * a.y + v.z * a.z + v.w * a.w;
        float pd = v.x * b.x + v.y * b.y + v.z * b.z + v.w * b.w;
#pragma unroll
        for (int o = 8; o > 0; o >>= 1) {
            ps += __shfl_xor_sync(0xffffffffu, ps, o);
            pd += __shfl_xor_sync(0xffffffffu, pd, o);
        }
        if (lane == 0)  { g_asrc[2 * w]     = ps; g_adst[2 * w]     = pd; }
        if (lane == 16) { g_asrc[2 * w + 1] = ps; g_adst[2 * w + 1] = pd; }
    } else {
        float4 v0 = row[lane],      a0 = as4[lane],      b0 = ad4[lane];
        float4 v1 = row[lane + 32], a1 = as4[lane + 32], b1 = ad4[lane + 32];
        float ps0 = v0.x * a0.x + v0.y * a0.y + v0.z * a0.z + v0.w * a0.w;
        float pd0 = v0.x * b0.x + v0.y * b0.y + v0.z * b0.z + v0.w * b0.w;
        float ps1 = v1.x * a1.x + v1.y * a1.y + v1.z * a1.z + v1.w * a1.w;
        float pd1 = v1.x * b1.x + v1.y * b1.y + v1.z * b1.z + v1.w * b1.w;
#pragma unroll
        for (int o = 16; o > 0; o >>= 1) {
            ps0 += __shfl_xor_sync(0xffffffffu, ps0, o);
            pd0 += __shfl_xor_sync(0xffffffffu, pd0, o);
            ps1 += __shfl_xor_sync(0xffffffffu, ps1, o);
            pd1 += __shfl_xor_sync(0xffffffffu, pd1, o);
        }
        if (lane == 0) {
            g_asrc[2 * w] = ps0; g_asrc[2 * w + 1] = ps1;
            g_adst[2 * w] = pd0; g_adst[2 * w + 1] = pd1;
        }
    }
}

// ---------------------------------------------------------------------------
// CSR construction.
// ---------------------------------------------------------------------------
__global__ void zero_cnt_kernel(int n)
{
    int i = blockIdx.x * blockDim.x + threadIdx.x;
    if (i < n) g_cnt[i] = 0;
}

__global__ void hist_kernel(const int* __restrict__ dst, int ne)
{
    int i = blockIdx.x * blockDim.x + threadIdx.x;
    if (i < ne) atomicAdd(&g_cnt[dst[i]], 1);
}

// 3-phase multi-block exclusive scan over g_cnt[n] (n <= 32*4096).
// Phase A: per-block (4096 elems) local exclusive scan -> g_rowptr, block sum.
__global__ __launch_bounds__(1024)
void scanA_kernel(int n)
{
    __shared__ int wsum[32];
    int tid = threadIdx.x, lane = tid & 31, wid = tid >> 5;
    int i0 = blockIdx.x * 4096 + tid * 4;

    int c0 = 0, c1 = 0, c2 = 0, c3 = 0;
    if (i0 + 3 < n) {
        int4 t = *(const int4*)&g_cnt[i0];
        c0 = t.x; c1 = t.y; c2 = t.z; c3 = t.w;
    } else {
        if (i0     < n) c0 = g_cnt[i0];
        if (i0 + 1 < n) c1 = g_cnt[i0 + 1];
        if (i0 + 2 < n) c2 = g_cnt[i0 + 2];
        if (i0 + 3 < n) c3 = g_cnt[i0 + 3];
    }
    int v = c0 + c1 + c2 + c3;
    int s = v;
#pragma unroll
    for (int o = 1; o < 32; o <<= 1) {
        int t = __shfl_up_sync(0xffffffffu, s, o);
        if (lane >= o) s += t;
    }
    if (lane == 31) wsum[wid] = s;
    __syncthreads();
    if (wid == 0) {
        int ws = wsum[lane];
#pragma unroll
        for (int o = 1; o < 32; o <<= 1) {
            int t = __shfl_up_sync(0xffffffffu, ws, o);
            if (lane >= o) ws += t;
        }
        wsum[lane] = ws;
    }
    __syncthreads();
    int excl = s - v + (wid ? wsum[wid - 1] : 0);
    int e0 = excl, e1 = e0 + c0, e2 = e1 + c1, e3 = e2 + c2;
    if (i0     < n) g_rowptr[i0]     = e0;
    if (i0 + 1 < n) g_rowptr[i0 + 1] = e1;
    if (i0 + 2 < n) g_rowptr[i0 + 2] = e2;
    if (i0 + 3 < n) g_rowptr[i0 + 3] = e3;
    if (tid == 0) g_bsum[blockIdx.x] = wsum[31];
}

// Phase B: one warp scans the block sums; writes grand total to g_rowptr[n].
__global__ void scanB_kernel(int nblocks, int n)
{
    int lane = threadIdx.x;
    int v = (lane < nblocks) ? g_bsum[lane] : 0;
    int s = v;
#pragma unroll
    for (int o = 1; o < 32; o <<= 1) {
        int t = __shfl_up_sync(0xffffffffu, s, o);
        if (lane >= o) s += t;
    }
    if (lane < nblocks) g_bsum_scan[lane] = s - v;
    if (lane == 31) g_rowptr[n] = s;
}

// Phase C: add block offsets; mirror into g_off.
__global__ void scanC_kernel(int n)
{
    int i = blockIdx.x * blockDim.x + threadIdx.x;
    if (i >= n) return;
    int v = g_rowptr[i] + g_bsum_scan[i >> 12];
    g_rowptr[i] = v;
    g_off[i] = v;
}

__global__ void scatter_kernel(const int* __restrict__ src, const int* __restrict__ dst, int ne)
{
    int i = blockIdx.x * blockDim.x + threadIdx.x;
    if (i >= ne) return;
    int pos = atomicAdd(&g_off[dst[i]], 1);
    g_col[pos] = src[i];
}

// ---------------------------------------------------------------------------
// Node kernel: warp per destination, chunked lane-parallel weights, shfl
// broadcast into the feature-gather loop.
// ---------------------------------------------------------------------------
template <int F>
__global__ __launch_bounds__(256)
void node_kernel(const float* __restrict__ xl, const float* __restrict__ bias,
                 float* __restrict__ out, int n_nodes)
{
    constexpr int FT = 2 * F;
    const unsigned FULL = 0xffffffffu;
    int w = (blockIdx.x * blockDim.x + threadIdx.x) >> 5;
    int lane = threadIdx.x & 31;
    if (w >= n_nodes) return;

    const int beg = g_rowptr[w], end = g_rowptr[w + 1];
    const int deg = end - beg;
    const float ad0 = g_adst[2 * w], ad1 = g_adst[2 * w + 1];
    const float aself0 = leaky(g_asrc[2 * w] + ad0);
    const float aself1 = leaky(g_asrc[2 * w + 1] + ad1);

    // accumulators
    float4 a0, a1;          // a1 used only for F==128
    const float4* xrow = (const float4*)(xl + (size_t)w * FT);
    float den0, den1;

    if (deg <= 32) {
        // ---- single-chunk fast path: alphas computed once, reused ----
        int i = beg + lane;
        bool vld = (i < end);
        int s_l = vld ? g_col[i] : 0;
        float al0 = -1e30f, al1 = -1e30f;
        if (vld) {
            al0 = leaky(g_asrc[2 * s_l]     + ad0);
            al1 = leaky(g_asrc[2 * s_l + 1] + ad1);
        }
        float m0 = fmaxf(al0, aself0), m1 = fmaxf(al1, aself1);
#pragma unroll
        for (int o = 16; o > 0; o >>= 1) {
            m0 = fmaxf(m0, __shfl_xor_sync(FULL, m0, o));
            m1 = fmaxf(m1, __shfl_xor_sync(FULL, m1, o));
        }
        float f0_l = vld ? __expf(al0 - m0) : 0.f;
        float f1_l = vld ? __expf(al1 - m1) : 0.f;
        float d0 = f0_l, d1 = f1_l;
#pragma unroll
        for (int o = 16; o > 0; o >>= 1) {
            d0 += __shfl_xor_sync(FULL, d0, o);
            d1 += __shfl_xor_sync(FULL, d1, o);
        }
        float e0 = __expf(aself0 - m0), e1 = __expf(aself1 - m1);
        den0 = d0 + e0; den1 = d1 + e1;

        if constexpr (F == 64) {
            float esel = (lane < 16) ? e0 : e1;
            float4 v = xrow[lane];
            a0 = make_float4(v.x * esel, v.y * esel, v.z * esel, v.w * esel);
#pragma unroll 4
            for (int e = 0; e < deg; e++) {
                int s   = __shfl_sync(FULL, s_l, e);
                float f0 = __shfl_sync(FULL, f0_l, e);
                float f1 = __shfl_sync(FULL, f1_l, e);
                float fe = (lane < 16) ? f0 : f1;
                float4 u = ((const float4*)(xl + (size_t)s * FT))[lane];
                a0.x += u.x * fe; a0.y += u.y * fe;
                a0.z += u.z * fe; a0.w += u.w * fe;
            }
        } else {
            float4 v0 = xrow[lane], v1 = xrow[lane + 32];
            a0 = make_float4(v0.x * e0, v0.y * e0, v0.z * e0, v0.w * e0);
            a1 = make_float4(v1.x * e1, v1.y * e1, v1.z * e1, v1.w * e1);
#pragma unroll 4
            for (int e = 0; e < deg; e++) {
                int s   = __shfl_sync(FULL, s_l, e);
                float f0 = __shfl_sync(FULL, f0_l, e);
                float f1 = __shfl_sync(FULL, f1_l, e);
                const float4* xs = (const float4*)(xl + (size_t)s * FT);
                float4 u0 = xs[lane], u1 = xs[lane + 32];
                a0.x += u0.x * f0; a0.y += u0.y * f0;
                a0.z += u0.z * f0; a0.w += u0.w * f0;
                a1.x += u1.x * f1; a1.y += u1.y * f1;
                a1.z += u1.z * f1; a1.w += u1.w * f1;
            }
        }
    } else {
        // ---- generic chunked path ----
        float m0 = aself0, m1 = aself1;
        for (int i = beg + lane; i < end; i += 32) {
            int s = g_col[i];
            m0 = fmaxf(m0, leaky(g_asrc[2 * s]     + ad0));
            m1 = fmaxf(m1, leaky(g_asrc[2 * s + 1] + ad1));
        }
#pragma unroll
        for (int o = 16; o > 0; o >>= 1) {
            m0 = fmaxf(m0, __shfl_xor_sync(FULL, m0, o));
            m1 = fmaxf(m1, __shfl_xor_sync(FULL, m1, o));
        }
        float e0 = __expf(aself0 - m0), e1 = __expf(aself1 - m1);
        float dp0 = 0.f, dp1 = 0.f;

        if constexpr (F == 64) {
            float esel = (lane < 16) ? e0 : e1;
            float4 v = xrow[lane];
            a0 = make_float4(v.x * esel, v.y * esel, v.z * esel, v.w * esel);
        } else {
            float4 v0 = xrow[lane], v1 = xrow[lane + 32];
            a0 = make_float4(v0.x * e0, v0.y * e0, v0.z * e0, v0.w * e0);
            a1 = make_float4(v1.x * e1, v1.y * e1, v1.z * e1, v1.w * e1);
        }

        for (int base = beg; base < end; base += 32) {
            int i = base + lane;
            bool vld = (i < end);
            int s_l = vld ? g_col[i] : 0;
            float f0_l = 0.f, f1_l = 0.f;
            if (vld) {
                f0_l = __expf(leaky(g_asrc[2 * s_l]     + ad0) - m0);
                f1_l = __expf(leaky(g_asrc[2 * s_l + 1] + ad1) - m1);
            }
            dp0 += f0_l; dp1 += f1_l;
            int cnt = min(32, end - base);
#pragma unroll 4
            for (int e = 0; e < cnt; e++) {
                int s   = __shfl_sync(FULL, s_l, e);
                float f0 = __shfl_sync(FULL, f0_l, e);
                float f1 = __shfl_sync(FULL, f1_l, e);
                if constexpr (F == 64) {
                    float fe = (lane < 16) ? f0 : f1;
                    float4 u = ((const float4*)(xl + (size_t)s * FT))[lane];
                    a0.x += u.x * fe; a0.y += u.y * fe;
                    a0.z += u.z * fe; a0.w += u.w * fe;
                } else {
                    const float4* xs = (const float4*)(xl + (size_t)s * FT);
                    float4 u0 = xs[lane], u1 = xs[lane + 32];
                    a0.x += u0.x * f0; a0.y += u0.y * f0;
                    a0.z += u0.z * f0; a0.w += u0.w * f0;
                    a1.x += u1.x * f1; a1.y += u1.y * f1;
                    a1.z += u1.z * f1; a1.w += u1.w * f1;
                }
            }
        }
#pragma unroll
        for (int o = 16; o > 0; o >>= 1) {
            dp0 += __shfl_xor_sync(FULL, dp0, o);
            dp1 += __shfl_xor_sync(FULL, dp1, o);
        }
        den0 = dp0 + e0; den1 = dp1 + e1;
    }

    // epilogue: divide + bias
    const float4* b4 = (const float4*)bias;
    float4* orow = (float4*)(out + (size_t)w * FT);
    if constexpr (F == 64) {
        float id = 1.f / ((lane < 16) ? den0 : den1);
        float4 bb = b4[lane];
        orow[lane] = make_float4(a0.x * id + bb.x, a0.y * id + bb.y,
                                 a0.z * id + bb.z, a0.w * id + bb.w);
    } else {
        float id0 = 1.f / den0, id1 = 1.f / den1;
        float4 b0 = b4[lane], b1 = b4[lane + 32];
        orow[lane]      = make_float4(a0.x * id0 + b0.x, a0.y * id0 + b0.y,
                                      a0.z * id0 + b0.z, a0.w * id0 + b0.w);
        orow[lane + 32] = make_float4(a1.x * id1 + b1.x, a1.y * id1 + b1.y,
                                      a1.z * id1 + b1.z, a1.w * id1 + b1.w);
    }
}

// ---------------------------------------------------------------------------

extern "C" void kernel_launch(void* const* d_in, const int* in_sizes, int n_in,
                              void* d_out, int out_size)
{
    const float* x   = (const float*)d_in[0];
    const int*   und = (const int*)d_in[1];
    const int*   dir = (const int*)d_in[2];
    const float* W1  = (const float*)d_in[3];
    const float* as1 = (const float*)d_in[4];
    const float* ad1 = (const float*)d_in[5];
    const float* b1  = (const float*)d_in[6];
    const float* W2  = (const float*)d_in[7];
    const float* as2 = (const float*)d_in[8];
    const float* ad2 = (const float*)d_in[9];
    const float* b2  = (const float*)d_in[10];
    float* out = (float*)d_out;

    const int n  = in_sizes[0] / 64;   // 50000
    const int e1 = in_sizes[1] / 2;    // 800000
    const int e2 = in_sizes[2] / 2;    // 800000

    float *xl1p, *out1p, *xl2p;
    cudaGetSymbolAddress((void**)&xl1p,  g_xl1);
    cudaGetSymbolAddress((void**)&out1p, g_out1);
    cudaGetSymbolAddress((void**)&xl2p,  g_xl2);

    const int T = 256;
    auto cdiv = [](long long a, long long b) { return (int)((a + b - 1) / b); };
    const int nsb = cdiv(n, 4096);     // scan blocks

    // ---------------- Layer 1 (F=64, FT=128) ----------------
    gemm_kernel<64, 128><<<cdiv(n, 64), T>>>(x, W1, xl1p, n);
    attn_kernel<64><<<cdiv((long long)n * 32, T), T>>>(xl1p, as1, ad1, n);
    zero_cnt_kernel<<<cdiv(n, T), T>>>(n);
    hist_kernel<<<cdiv(e1, T), T>>>(und + e1, e1);
    scanA_kernel<<<nsb, 1024>>>(n);
    scanB_kernel<<<1, 32>>>(nsb, n);
    scanC_kernel<<<cdiv(n, T), T>>>(n);
    scatter_kernel<<<cdiv(e1, T), T>>>(und, und + e1, e1);
    node_kernel<64><<<cdiv((long long)n * 32, T), T>>>(xl1p, b1, out1p, n);

    // ---------------- Layer 2 (F=128, FT=256) ----------------
    gemm_kernel<128, 256><<<cdiv(n, 64), T>>>(out1p, W2, xl2p, n);
    attn_kernel<128><<<cdiv((long long)n * 32, T), T>>>(xl2p, as2, ad2, n);
    zero_cnt_kernel<<<cdiv(n, T), T>>>(n);
    hist_kernel<<<cdiv(e2, T), T>>>(dir + e2, e2);
    scanA_kernel<<<nsb, 1024>>>(n);
    scanB_kernel<<<1, 32>>>(nsb, n);
    scanC_kernel<<<cdiv(n, T), T>>>(n);
    scatter_kernel<<<cdiv(e2, T), T>>>(dir, dir + e2, e2);
    node_kernel<128><<<cdiv((long long)n * 32, T), T>>>(xl2p, b2, out, n);
}

// round 8
// speedup vs baseline: 1.2450x; 1.0450x over previous
#include <cuda_runtime.h>
#include <cstdint>

// ---------------------------------------------------------------------------
// 2-layer GAT (heads=2), CSR-based, packed-f32x2 SIMT GEMM (FFMA2), chunked
// node softmax-aggregate.
// ---------------------------------------------------------------------------

#define NN 50000
#define NE 800000

typedef unsigned long long ull;

__device__ float g_xl1[NN * 128];
__device__ float g_out1[NN * 128];
__device__ float g_xl2[NN * 256];
__device__ float g_asrc[NN * 2];
__device__ float g_adst[NN * 2];
__device__ int   g_cnt[NN];
__device__ int   g_rowptr[NN + 1];
__device__ int   g_off[NN];
__device__ int   g_col[NE];
__device__ int   g_bsum[32];
__device__ int   g_bsum_scan[32];

__device__ __forceinline__ float leaky(float a) { return a > 0.f ? a : 0.2f * a; }

__device__ __forceinline__ void fma_f32x2(ull& c, ull a, ull b) {
    asm("fma.rn.f32x2 %0, %1, %2, %0;" : "+l"(c) : "l"(a), "l"(b));
}
__device__ __forceinline__ float2 unpack2(ull v) {
    float lo, hi;
    asm("mov.b64 {%0,%1}, %2;" : "=f"(lo), "=f"(hi) : "l"(v));
    return make_float2(lo, hi);
}

// ---------------------------------------------------------------------------
// Packed GEMM: C[M,NC] = A[M,KTOT] @ B[KTOT,NC].  TM=64, BK=32, 256 threads.
// A tile duplicated into float2 {v,v}; thread covers cols 64*j2 + 2*tx(+1).
// ---------------------------------------------------------------------------
template <int KTOT, int NC>
__global__ __launch_bounds__(256)
void gemm_kernel(const float* __restrict__ A, const float* __restrict__ B,
                 float* __restrict__ C, int M)
{
    constexpr int TM = 64, BK = 32;
    constexpr int RM = 8;
    constexpr int RN2 = NC / 64;      // packed col-pairs per thread

    __shared__ float2 sA2[BK][TM + 1];
    __shared__ float  sB[BK][NC];

    const int tid = threadIdx.x;
    const int tx = tid & 31, ty = tid >> 5;
    const int m0 = blockIdx.x * TM;

    ull acc2[RM][RN2];
#pragma unroll
    for (int i = 0; i < RM; i++)
#pragma unroll
        for (int j = 0; j < RN2; j++) acc2[i][j] = 0ull;

    for (int k0 = 0; k0 < KTOT; k0 += BK) {
        // load A tile (64 x 32), duplicate each value into float2
#pragma unroll
        for (int i = 0; i < (TM * BK) / 256; i++) {
            int idx = tid + 256 * i;
            int r = idx >> 5;
            int kk = idx & 31;
            int row = m0 + r;
            float v = (row < M) ? A[(size_t)row * KTOT + k0 + kk] : 0.f;
            sA2[kk][r] = make_float2(v, v);
        }
        // load B tile (32 x NC)
#pragma unroll
        for (int i = 0; i < (BK * NC) / 256; i++) {
            int idx = tid + 256 * i;
            int kk = idx / NC;
            int c  = idx % NC;
            sB[kk][c] = B[(size_t)(k0 + kk) * NC + c];
        }
        __syncthreads();

#pragma unroll 4
        for (int kk = 0; kk < BK; kk++) {
            ull xv[RM], wv[RN2];
#pragma unroll
            for (int i = 0; i < RM; i++)
                xv[i] = *(const ull*)&sA2[kk][ty * RM + i];
#pragma unroll
            for (int j = 0; j < RN2; j++)
                wv[j] = *(const ull*)&sB[kk][64 * j + 2 * tx];
#pragma unroll
            for (int i = 0; i < RM; i++)
#pragma unroll
                for (int j = 0; j < RN2; j++)
                    fma_f32x2(acc2[i][j], xv[i], wv[j]);
        }
        __syncthreads();
    }

#pragma unroll
    for (int i = 0; i < RM; i++) {
        int row = m0 + ty * RM + i;
        if (row < M) {
#pragma unroll
            for (int j = 0; j < RN2; j++)
                *(float2*)&C[(size_t)row * NC + 64 * j + 2 * tx] = unpack2(acc2[i][j]);
        }
    }
}

// ---------------------------------------------------------------------------
// Attention coefficients: warp per node.
// ---------------------------------------------------------------------------
template <int F>
__global__ void attn_kernel(const float* __restrict__ xl,
                            const float* __restrict__ att_s,
                            const float* __restrict__ att_d,
                            int n_nodes)
{
    constexpr int FT = 2 * F;
    int w = (blockIdx.x * blockDim.x + threadIdx.x) >> 5;
    int lane = threadIdx.x & 31;
    if (w >= n_nodes) return;

    const float4* row = (const float4*)(xl + (size_t)w * FT);
    const float4* as4 = (const float4*)att_s;
    const float4* ad4 = (const float4*)att_d;

    if constexpr (F == 64) {
        float4 v = row[lane], a = as4[lane], b = ad4[lane];
        float ps = v.x * a.x + v.y * a.y + v.z * a.z + v.w * a.w;
        float pd = v.x * b.x + v.y * b.y + v.z * b.z + v.w * b.w;
#pragma unroll
        for (int o = 8; o > 0; o >>= 1) {
            ps += __shfl_xor_sync(0xffffffffu, ps, o);
            pd += __shfl_xor_sync(0xffffffffu, pd, o);
        }
        if (lane == 0)  { g_asrc[2 * w]     = ps; g_adst[2 * w]     = pd; }
        if (lane == 16) { g_asrc[2 * w + 1] = ps; g_adst[2 * w + 1] = pd; }
    } else {
        float4 v0 = row[lane],      a0 = as4[lane],      b0 = ad4[lane];
        float4 v1 = row[lane + 32], a1 = as4[lane + 32], b1 = ad4[lane + 32];
        float ps0 = v0.x * a0.x + v0.y * a0.y + v0.z * a0.z + v0.w * a0.w;
        float pd0 = v0.x * b0.x + v0.y * b0.y + v0.z * b0.z + v0.w * b0.w;
        float ps1 = v1.x * a1.x + v1.y * a1.y + v1.z * a1.z + v1.w * a1.w;
        float pd1 = v1.x * b1.x + v1.y * b1.y + v1.z * b1.z + v1.w * b1.w;
#pragma unroll
        for (int o = 16; o > 0; o >>= 1) {
            ps0 += __shfl_xor_sync(0xffffffffu, ps0, o);
            pd0 += __shfl_xor_sync(0xffffffffu, pd0, o);
            ps1 += __shfl_xor_sync(0xffffffffu, ps1, o);
            pd1 += __shfl_xor_sync(0xffffffffu, pd1, o);
        }
        if (lane == 0) {
            g_asrc[2 * w] = ps0; g_asrc[2 * w + 1] = ps1;
            g_adst[2 * w] = pd0; g_adst[2 * w + 1] = pd1;
        }
    }
}

// ---------------------------------------------------------------------------
// CSR construction.
// ---------------------------------------------------------------------------
__global__ void zero_cnt_kernel(int n)
{
    int i = blockIdx.x * blockDim.x + threadIdx.x;
    if (i < n) g_cnt[i] = 0;
}

__global__ void hist_kernel(const int* __restrict__ dst, int ne)
{
    int i = blockIdx.x * blockDim.x + threadIdx.x;
    if (i < ne) atomicAdd(&g_cnt[dst[i]], 1);
}

__global__ __launch_bounds__(1024)
void scanA_kernel(int n)
{
    __shared__ int wsum[32];
    int tid = threadIdx.x, lane = tid & 31, wid = tid >> 5;
    int i0 = blockIdx.x * 4096 + tid * 4;

    int c0 = 0, c1 = 0, c2 = 0, c3 = 0;
    if (i0 + 3 < n) {
        int4 t = *(const int4*)&g_cnt[i0];
        c0 = t.x; c1 = t.y; c2 = t.z; c3 = t.w;
    } else {
        if (i0     < n) c0 = g_cnt[i0];
        if (i0 + 1 < n) c1 = g_cnt[i0 + 1];
        if (i0 + 2 < n) c2 = g_cnt[i0 + 2];
        if (i0 + 3 < n) c3 = g_cnt[i0 + 3];
    }
    int v = c0 + c1 + c2 + c3;
    int s = v;
#pragma unroll
    for (int o = 1; o < 32; o <<= 1) {
        int t = __shfl_up_sync(0xffffffffu, s, o);
        if (lane >= o) s += t;
    }
    if (lane == 31) wsum[wid] = s;
    __syncthreads();
    if (wid == 0) {
        int ws = wsum[lane];
#pragma unroll
        for (int o = 1; o < 32; o <<= 1) {
            int t = __shfl_up_sync(0xffffffffu, ws, o);
            if (lane >= o) ws += t;
        }
        wsum[lane] = ws;
    }
    __syncthreads();
    int excl = s - v + (wid ? wsum[wid - 1] : 0);
    int e0 = excl, e1 = e0 + c0, e2 = e1 + c1, e3 = e2 + c2;
    if (i0     < n) g_rowptr[i0]     = e0;
    if (i0 + 1 < n) g_rowptr[i0 + 1] = e1;
    if (i0 + 2 < n) g_rowptr[i0 + 2] = e2;
    if (i0 + 3 < n) g_rowptr[i0 + 3] = e3;
    if (tid == 0) g_bsum[blockIdx.x] = wsum[31];
}

__global__ void scanB_kernel(int nblocks, int n)
{
    int lane = threadIdx.x;
    int v = (lane < nblocks) ? g_bsum[lane] : 0;
    int s = v;
#pragma unroll
    for (int o = 1; o < 32; o <<= 1) {
        int t = __shfl_up_sync(0xffffffffu, s, o);
        if (lane >= o) s += t;
    }
    if (lane < nblocks) g_bsum_scan[lane] = s - v;
    if (lane == 31) g_rowptr[n] = s;
}

__global__ void scanC_kernel(int n)
{
    int i = blockIdx.x * blockDim.x + threadIdx.x;
    if (i >= n) return;
    int v = g_rowptr[i] + g_bsum_scan[i >> 12];
    g_rowptr[i] = v;
    g_off[i] = v;
}

__global__ void scatter_kernel(const int* __restrict__ src, const int* __restrict__ dst, int ne)
{
    int i = blockIdx.x * blockDim.x + threadIdx.x;
    if (i >= ne) return;
    int pos = atomicAdd(&g_off[dst[i]], 1);
    g_col[pos] = src[i];
}

// ---------------------------------------------------------------------------
// Node kernel: warp per destination, chunked lane-parallel weights, shfl
// broadcast into the feature-gather loop.
// ---------------------------------------------------------------------------
template <int F>
__global__ __launch_bounds__(256)
void node_kernel(const float* __restrict__ xl, const float* __restrict__ bias,
                 float* __restrict__ out, int n_nodes)
{
    constexpr int FT = 2 * F;
    const unsigned FULL = 0xffffffffu;
    int w = (blockIdx.x * blockDim.x + threadIdx.x) >> 5;
    int lane = threadIdx.x & 31;
    if (w >= n_nodes) return;

    const int beg = g_rowptr[w], end = g_rowptr[w + 1];
    const int deg = end - beg;
    const float ad0 = g_adst[2 * w], ad1 = g_adst[2 * w + 1];
    const float aself0 = leaky(g_asrc[2 * w] + ad0);
    const float aself1 = leaky(g_asrc[2 * w + 1] + ad1);

    float4 a0, a1;
    const float4* xrow = (const float4*)(xl + (size_t)w * FT);
    float den0, den1;

    if (deg <= 32) {
        int i = beg + lane;
        bool vld = (i < end);
        int s_l = vld ? g_col[i] : 0;
        float al0 = -1e30f, al1 = -1e30f;
        if (vld) {
            al0 = leaky(g_asrc[2 * s_l]     + ad0);
            al1 = leaky(g_asrc[2 * s_l + 1] + ad1);
        }
        float m0 = fmaxf(al0, aself0), m1 = fmaxf(al1, aself1);
#pragma unroll
        for (int o = 16; o > 0; o >>= 1) {
            m0 = fmaxf(m0, __shfl_xor_sync(FULL, m0, o));
            m1 = fmaxf(m1, __shfl_xor_sync(FULL, m1, o));
        }
        float f0_l = vld ? __expf(al0 - m0) : 0.f;
        float f1_l = vld ? __expf(al1 - m1) : 0.f;
        float d0 = f0_l, d1 = f1_l;
#pragma unroll
        for (int o = 16; o > 0; o >>= 1) {
            d0 += __shfl_xor_sync(FULL, d0, o);
            d1 += __shfl_xor_sync(FULL, d1, o);
        }
        float e0 = __expf(aself0 - m0), e1 = __expf(aself1 - m1);
        den0 = d0 + e0; den1 = d1 + e1;

        if constexpr (F == 64) {
            float esel = (lane < 16) ? e0 : e1;
            float4 v = xrow[lane];
            a0 = make_float4(v.x * esel, v.y * esel, v.z * esel, v.w * esel);
#pragma unroll 4
            for (int e = 0; e < deg; e++) {
                int s   = __shfl_sync(FULL, s_l, e);
                float f0 = __shfl_sync(FULL, f0_l, e);
                float f1 = __shfl_sync(FULL, f1_l, e);
                float fe = (lane < 16) ? f0 : f1;
                float4 u = ((const float4*)(xl + (size_t)s * FT))[lane];
                a0.x += u.x * fe; a0.y += u.y * fe;
                a0.z += u.z * fe; a0.w += u.w * fe;
            }
        } else {
            float4 v0 = xrow[lane], v1 = xrow[lane + 32];
            a0 = make_float4(v0.x * e0, v0.y * e0, v0.z * e0, v0.w * e0);
            a1 = make_float4(v1.x * e1, v1.y * e1, v1.z * e1, v1.w * e1);
#pragma unroll 4
            for (int e = 0; e < deg; e++) {
                int s   = __shfl_sync(FULL, s_l, e);
                float f0 = __shfl_sync(FULL, f0_l, e);
                float f1 = __shfl_sync(FULL, f1_l, e);
                const float4* xs = (const float4*)(xl + (size_t)s * FT);
                float4 u0 = xs[lane], u1 = xs[lane + 32];
                a0.x += u0.x * f0; a0.y += u0.y * f0;
                a0.z += u0.z * f0; a0.w += u0.w * f0;
                a1.x += u1.x * f1; a1.y += u1.y * f1;
                a1.z += u1.z * f1; a1.w += u1.w * f1;
            }
        }
    } else {
        float m0 = aself0, m1 = aself1;
        for (int i = beg + lane; i < end; i += 32) {
            int s = g_col[i];
            m0 = fmaxf(m0, leaky(g_asrc[2 * s]     + ad0));
            m1 = fmaxf(m1, leaky(g_asrc[2 * s + 1] + ad1));
        }
#pragma unroll
        for (int o = 16; o > 0; o >>= 1) {
            m0 = fmaxf(m0, __shfl_xor_sync(FULL, m0, o));
            m1 = fmaxf(m1, __shfl_xor_sync(FULL, m1, o));
        }
        float e0 = __expf(aself0 - m0), e1 = __expf(aself1 - m1);
        float dp0 = 0.f, dp1 = 0.f;

        if constexpr (F == 64) {
            float esel = (lane < 16) ? e0 : e1;
            float4 v = xrow[lane];
            a0 = make_float4(v.x * esel, v.y * esel, v.z * esel, v.w * esel);
        } else {
            float4 v0 = xrow[lane], v1 = xrow[lane + 32];
            a0 = make_float4(v0.x * e0, v0.y * e0, v0.z * e0, v0.w * e0);
            a1 = make_float4(v1.x * e1, v1.y * e1, v1.z * e1, v1.w * e1);
        }

        for (int base = beg; base < end; base += 32) {
            int i = base + lane;
            bool vld = (i < end);
            int s_l = vld ? g_col[i] : 0;
            float f0_l = 0.f, f1_l = 0.f;
            if (vld) {
                f0_l = __expf(leaky(g_asrc[2 * s_l]     + ad0) - m0);
                f1_l = __expf(leaky(g_asrc[2 * s_l + 1] + ad1) - m1);
            }
            dp0 += f0_l; dp1 += f1_l;
            int cnt = min(32, end - base);
#pragma unroll 4
            for (int e = 0; e < cnt; e++) {
                int s   = __shfl_sync(FULL, s_l, e);
                float f0 = __shfl_sync(FULL, f0_l, e);
                float f1 = __shfl_sync(FULL, f1_l, e);
                if constexpr (F == 64) {
                    float fe = (lane < 16) ? f0 : f1;
                    float4 u = ((const float4*)(xl + (size_t)s * FT))[lane];
                    a0.x += u.x * fe; a0.y += u.y * fe;
                    a0.z += u.z * fe; a0.w += u.w * fe;
                } else {
                    const float4* xs = (const float4*)(xl + (size_t)s * FT);
                    float4 u0 = xs[lane], u1 = xs[lane + 32];
                    a0.x += u0.x * f0; a0.y += u0.y * f0;
                    a0.z += u0.z * f0; a0.w += u0.w * f0;
                    a1.x += u1.x * f1; a1.y += u1.y * f1;
                    a1.z += u1.z * f1; a1.w += u1.w * f1;
                }
            }
        }
#pragma unroll
        for (int o = 16; o > 0; o >>= 1) {
            dp0 += __shfl_xor_sync(FULL, dp0, o);
            dp1 += __shfl_xor_sync(FULL, dp1, o);
        }
        den0 = dp0 + e0; den1 = dp1 + e1;
    }

    const float4* b4 = (const float4*)bias;
    float4* orow = (float4*)(out + (size_t)w * FT);
    if constexpr (F == 64) {
        float id = 1.f / ((lane < 16) ? den0 : den1);
        float4 bb = b4[lane];
        orow[lane] = make_float4(a0.x * id + bb.x, a0.y * id + bb.y,
                                 a0.z * id + bb.z, a0.w * id + bb.w);
    } else {
        float id0 = 1.f / den0, id1 = 1.f / den1;
        float4 b0 = b4[lane], b1 = b4[lane + 32];
        orow[lane]      = make_float4(a0.x * id0 + b0.x, a0.y * id0 + b0.y,
                                      a0.z * id0 + b0.z, a0.w * id0 + b0.w);
        orow[lane + 32] = make_float4(a1.x * id1 + b1.x, a1.y * id1 + b1.y,
                                      a1.z * id1 + b1.z, a1.w * id1 + b1.w);
    }
}

// ---------------------------------------------------------------------------

extern "C" void kernel_launch(void* const* d_in, const int* in_sizes, int n_in,
                              void* d_out, int out_size)
{
    const float* x   = (const float*)d_in[0];
    const int*   und = (const int*)d_in[1];
    const int*   dir = (const int*)d_in[2];
    const float* W1  = (const float*)d_in[3];
    const float* as1 = (const float*)d_in[4];
    const float* ad1 = (const float*)d_in[5];
    const float* b1  = (const float*)d_in[6];
    const float* W2  = (const float*)d_in[7];
    const float* as2 = (const float*)d_in[8];
    const float* ad2 = (const float*)d_in[9];
    const float* b2  = (const float*)d_in[10];
    float* out = (float*)d_out;

    const int n  = in_sizes[0] / 64;   // 50000
    const int e1 = in_sizes[1] / 2;    // 800000
    const int e2 = in_sizes[2] / 2;    // 800000

    float *xl1p, *out1p, *xl2p;
    cudaGetSymbolAddress((void**)&xl1p,  g_xl1);
    cudaGetSymbolAddress((void**)&out1p, g_out1);
    cudaGetSymbolAddress((void**)&xl2p,  g_xl2);

    const int T = 256;
    auto cdiv = [](long long a, long long b) { return (int)((a + b - 1) / b); };
    const int nsb = cdiv(n, 4096);

    // ---------------- Layer 1 (F=64, FT=128) ----------------
    gemm_kernel<64, 128><<<cdiv(n, 64), T>>>(x, W1, xl1p, n);
    attn_kernel<64><<<cdiv((long long)n * 32, T), T>>>(xl1p, as1, ad1, n);
    zero_cnt_kernel<<<cdiv(n, T), T>>>(n);
    hist_kernel<<<cdiv(e1, T), T>>>(und + e1, e1);
    scanA_kernel<<<nsb, 1024>>>(n);
    scanB_kernel<<<1, 32>>>(nsb, n);
    scanC_kernel<<<cdiv(n, T), T>>>(n);
    scatter_kernel<<<cdiv(e1, T), T>>>(und, und + e1, e1);
    node_kernel<64><<<cdiv((long long)n * 32, T), T>>>(xl1p, b1, out1p, n);

    // ---------------- Layer 2 (F=128, FT=256) ----------------
    gemm_kernel<128, 256><<<cdiv(n, 64), T>>>(out1p, W2, xl2p, n);
    attn_kernel<128><<<cdiv((long long)n * 32, T), T>>>(xl2p, as2, ad2, n);
    zero_cnt_kernel<<<cdiv(n, T), T>>>(n);
    hist_kernel<<<cdiv(e2, T), T>>>(dir + e2, e2);
    scanA_kernel<<<nsb, 1024>>>(n);
    scanB_kernel<<<1, 32>>>(nsb, n);
    scanC_kernel<<<cdiv(n, T), T>>>(n);
    scatter_kernel<<<cdiv(e2, T), T>>>(dir, dir + e2, e2);
    node_kernel<128><<<cdiv((long long)n * 32, T), T>>>(xl2p, b2, out, n);
}

// round 12
// speedup vs baseline: 1.3178x; 1.0585x over previous
#include <cuda_runtime.h>
#include <cstdint>

// ---------------------------------------------------------------------------
// 2-layer GAT (heads=2), CSR-based. FFMA2 GEMM with fused attention epilogue,
// packed-f32x2 node softmax-aggregate, self-zeroing CSR counters.
// ---------------------------------------------------------------------------

#define NN 50000
#define NE 800000

typedef unsigned long long ull;

__device__ float g_xl1[NN * 128];
__device__ float g_out1[NN * 128];
__device__ float g_xl2[NN * 256];
__device__ float g_asrc[NN * 2];
__device__ float g_adst[NN * 2];
__device__ int   g_cnt[NN];          // must be zero at entry; scanC re-zeroes
__device__ int   g_rowptr[NN + 1];
__device__ int   g_off[NN];
__device__ int   g_col[NE];
__device__ int   g_bsum[32];
__device__ int   g_bsum_scan[32];

__device__ __forceinline__ float leaky(float a) { return a > 0.f ? a : 0.2f * a; }

__device__ __forceinline__ void fma_f32x2(ull& c, ull a, ull b) {
    asm("fma.rn.f32x2 %0, %1, %2, %0;" : "+l"(c) : "l"(a), "l"(b));
}
__device__ __forceinline__ float2 unpack2(ull v) {
    float lo, hi;
    asm("mov.b64 {%0,%1}, %2;" : "=f"(lo), "=f"(hi) : "l"(v));
    return make_float2(lo, hi);
}
__device__ __forceinline__ ull pack2(float f) {
    ull r;
    asm("mov.b64 %0, {%1,%1};" : "=l"(r) : "f"(f));
    return r;
}

// ---------------------------------------------------------------------------
// Packed GEMM + fused attention epilogue.
// C[M,NC] = A[M,KTOT] @ B[KTOT,NC]; then a_src/a_dst per (row, head).
// TM=64, BK=32, 256 threads. Warp ty owns rows ty*8..+7 across ALL NC cols.
// ---------------------------------------------------------------------------
template <int KTOT, int NC>
__global__ __launch_bounds__(256)
void gemm_kernel(const float* __restrict__ A, const float* __restrict__ B,
                 const float* __restrict__ att_s, const float* __restrict__ att_d,
                 float* __restrict__ C, int M)
{
    constexpr int TM = 64, BK = 32;
    constexpr int RM = 8;
    constexpr int RN2 = NC / 64;
    const unsigned FULL = 0xffffffffu;

    __shared__ float2 sA2[BK][TM + 1];
    __shared__ float  sB[BK][NC];

    const int tid = threadIdx.x;
    const int tx = tid & 31, ty = tid >> 5;
    const int m0 = blockIdx.x * TM;

    ull acc2[RM][RN2];
#pragma unroll
    for (int i = 0; i < RM; i++)
#pragma unroll
        for (int j = 0; j < RN2; j++) acc2[i][j] = 0ull;

    for (int k0 = 0; k0 < KTOT; k0 += BK) {
#pragma unroll
        for (int i = 0; i < (TM * BK) / 256; i++) {
            int idx = tid + 256 * i;
            int r = idx >> 5;
            int kk = idx & 31;
            int row = m0 + r;
            float v = (row < M) ? A[(size_t)row * KTOT + k0 + kk] : 0.f;
            sA2[kk][r] = make_float2(v, v);
        }
#pragma unroll
        for (int i = 0; i < (BK * NC) / 256; i++) {
            int idx = tid + 256 * i;
            int kk = idx / NC;
            int c  = idx % NC;
            sB[kk][c] = B[(size_t)(k0 + kk) * NC + c];
        }
        __syncthreads();

#pragma unroll 4
        for (int kk = 0; kk < BK; kk++) {
            ull xv[RM], wv[RN2];
#pragma unroll
            for (int i = 0; i < RM; i++)
                xv[i] = *(const ull*)&sA2[kk][ty * RM + i];
#pragma unroll
            for (int j = 0; j < RN2; j++)
                wv[j] = *(const ull*)&sB[kk][64 * j + 2 * tx];
#pragma unroll
            for (int i = 0; i < RM; i++)
#pragma unroll
                for (int j = 0; j < RN2; j++)
                    fma_f32x2(acc2[i][j], xv[i], wv[j]);
        }
        __syncthreads();
    }

    // fused epilogue: store C, compute a_src/a_dst per row & head
    float2 asv[RN2], adv[RN2];
#pragma unroll
    for (int j = 0; j < RN2; j++) {
        asv[j] = *(const float2*)&att_s[64 * j + 2 * tx];
        adv[j] = *(const float2*)&att_d[64 * j + 2 * tx];
    }
#pragma unroll
    for (int i = 0; i < RM; i++) {
        int row = m0 + ty * RM + i;
        if (row >= M) continue;
        float s0 = 0.f, s1 = 0.f, d0 = 0.f, d1 = 0.f;
#pragma unroll
        for (int j = 0; j < RN2; j++) {
            float2 c = unpack2(acc2[i][j]);
            *(float2*)&C[(size_t)row * NC + 64 * j + 2 * tx] = c;
            float ps = c.x * asv[j].x + c.y * asv[j].y;
            float pd = c.x * adv[j].x + c.y * adv[j].y;
            if (j < RN2 / 2) { s0 += ps; d0 += pd; }
            else             { s1 += ps; d1 += pd; }
        }
#pragma unroll
        for (int o = 16; o > 0; o >>= 1) {
            s0 += __shfl_xor_sync(FULL, s0, o);
            s1 += __shfl_xor_sync(FULL, s1, o);
            d0 += __shfl_xor_sync(FULL, d0, o);
            d1 += __shfl_xor_sync(FULL, d1, o);
        }
        if (tx == 0) {
            g_asrc[2 * row] = s0; g_asrc[2 * row + 1] = s1;
            g_adst[2 * row] = d0; g_adst[2 * row + 1] = d1;
        }
    }
}

// ---------------------------------------------------------------------------
// CSR construction. g_cnt is pre-zeroed (static init / scanC re-zero).
// ---------------------------------------------------------------------------
__global__ void hist_kernel(const int* __restrict__ dst, int ne)
{
    int i = blockIdx.x * blockDim.x + threadIdx.x;
    if (i < ne) atomicAdd(&g_cnt[dst[i]], 1);
}

__global__ __launch_bounds__(1024)
void scanA_kernel(int n)
{
    __shared__ int wsum[32];
    int tid = threadIdx.x, lane = tid & 31, wid = tid >> 5;
    int i0 = blockIdx.x * 4096 + tid * 4;

    int c0 = 0, c1 = 0, c2 = 0, c3 = 0;
    if (i0 + 3 < n) {
        int4 t = *(const int4*)&g_cnt[i0];
        c0 = t.x; c1 = t.y; c2 = t.z; c3 = t.w;
    } else {
        if (i0     < n) c0 = g_cnt[i0];
        if (i0 + 1 < n) c1 = g_cnt[i0 + 1];
        if (i0 + 2 < n) c2 = g_cnt[i0 + 2];
        if (i0 + 3 < n) c3 = g_cnt[i0 + 3];
    }
    int v = c0 + c1 + c2 + c3;
    int s = v;
#pragma unroll
    for (int o = 1; o < 32; o <<= 1) {
        int t = __shfl_up_sync(0xffffffffu, s, o);
        if (lane >= o) s += t;
    }
    if (lane == 31) wsum[wid] = s;
    __syncthreads();
    if (wid == 0) {
        int ws = wsum[lane];
#pragma unroll
        for (int o = 1; o < 32; o <<= 1) {
            int t = __shfl_up_sync(0xffffffffu, ws, o);
            if (lane >= o) ws += t;
        }
        wsum[lane] = ws;
    }
    __syncthreads();
    int excl = s - v + (wid ? wsum[wid - 1] : 0);
    int e0 = excl, e1 = e0 + c0, e2 = e1 + c1, e3 = e2 + c2;
    if (i0     < n) g_rowptr[i0]     = e0;
    if (i0 + 1 < n) g_rowptr[i0 + 1] = e1;
    if (i0 + 2 < n) g_rowptr[i0 + 2] = e2;
    if (i0 + 3 < n) g_rowptr[i0 + 3] = e3;
    if (tid == 0) g_bsum[blockIdx.x] = wsum[31];
}

__global__ void scanB_kernel(int nblocks, int n)
{
    int lane = threadIdx.x;
    int v = (lane < nblocks) ? g_bsum[lane] : 0;
    int s = v;
#pragma unroll
    for (int o = 1; o < 32; o <<= 1) {
        int t = __shfl_up_sync(0xffffffffu, s, o);
        if (lane >= o) s += t;
    }
    if (lane < nblocks) g_bsum_scan[lane] = s - v;
    if (lane == 31) g_rowptr[n] = s;
}

// Phase C: add block offsets; mirror into g_off; re-zero g_cnt for next build.
__global__ void scanC_kernel(int n)
{
    int i = blockIdx.x * blockDim.x + threadIdx.x;
    if (i >= n) return;
    int v = g_rowptr[i] + g_bsum_scan[i >> 12];
    g_rowptr[i] = v;
    g_off[i] = v;
    g_cnt[i] = 0;
}

__global__ void scatter_kernel(const int* __restrict__ src, const int* __restrict__ dst, int ne)
{
    int i = blockIdx.x * blockDim.x + threadIdx.x;
    if (i >= ne) return;
    int pos = atomicAdd(&g_off[dst[i]], 1);
    g_col[pos] = src[i];
}

// ---------------------------------------------------------------------------
// Node kernel: warp per destination, chunked lane-parallel weights, shfl
// broadcast, packed-f32x2 accumulation.
// ---------------------------------------------------------------------------
template <int F>
__global__ __launch_bounds__(256)
void node_kernel(const float* __restrict__ xl, const float* __restrict__ bias,
                 float* __restrict__ out, int n_nodes)
{
    constexpr int FT = 2 * F;
    const unsigned FULL = 0xffffffffu;
    int w = (blockIdx.x * blockDim.x + threadIdx.x) >> 5;
    int lane = threadIdx.x & 31;
    if (w >= n_nodes) return;

    const int beg = g_rowptr[w], end = g_rowptr[w + 1];
    const int deg = end - beg;
    const float ad0 = g_adst[2 * w], ad1 = g_adst[2 * w + 1];
    const float aself0 = leaky(g_asrc[2 * w] + ad0);
    const float aself1 = leaky(g_asrc[2 * w + 1] + ad1);

    // packed accumulators: F==64 -> A[0..1]; F==128 -> A[0..3]
    ull A0 = 0ull, A1 = 0ull, A2 = 0ull, A3 = 0ull;
    const ulonglong2* xrow = (const ulonglong2*)(xl + (size_t)w * FT);
    float den0, den1;

    if (deg <= 32) {
        int i = beg + lane;
        bool vld = (i < end);
        int s_l = vld ? g_col[i] : 0;
        float al0 = -1e30f, al1 = -1e30f;
        if (vld) {
            al0 = leaky(g_asrc[2 * s_l]     + ad0);
            al1 = leaky(g_asrc[2 * s_l + 1] + ad1);
        }
        float m0 = fmaxf(al0, aself0), m1 = fmaxf(al1, aself1);
#pragma unroll
        for (int o = 16; o > 0; o >>= 1) {
            m0 = fmaxf(m0, __shfl_xor_sync(FULL, m0, o));
            m1 = fmaxf(m1, __shfl_xor_sync(FULL, m1, o));
        }
        float f0_l = vld ? __expf(al0 - m0) : 0.f;
        float f1_l = vld ? __expf(al1 - m1) : 0.f;
        float d0 = f0_l, d1 = f1_l;
#pragma unroll
        for (int o = 16; o > 0; o >>= 1) {
            d0 += __shfl_xor_sync(FULL, d0, o);
            d1 += __shfl_xor_sync(FULL, d1, o);
        }
        float e0 = __expf(aself0 - m0), e1 = __expf(aself1 - m1);
        den0 = d0 + e0; den1 = d1 + e1;

        if constexpr (F == 64) {
            ull ep = pack2((lane < 16) ? e0 : e1);
            ulonglong2 v = xrow[lane];
            fma_f32x2(A0, v.x, ep);
            fma_f32x2(A1, v.y, ep);
#pragma unroll 4
            for (int e = 0; e < deg; e++) {
                int s    = __shfl_sync(FULL, s_l, e);
                float f0 = __shfl_sync(FULL, f0_l, e);
                float f1 = __shfl_sync(FULL, f1_l, e);
                ull fp = pack2((lane < 16) ? f0 : f1);
                ulonglong2 u = ((const ulonglong2*)(xl + (size_t)s * FT))[lane];
                fma_f32x2(A0, u.x, fp);
                fma_f32x2(A1, u.y, fp);
            }
        } else {
            ull e0p = pack2(e0), e1p = pack2(e1);
            ulonglong2 v0 = xrow[lane], v1 = xrow[lane + 32];
            fma_f32x2(A0, v0.x, e0p); fma_f32x2(A1, v0.y, e0p);
            fma_f32x2(A2, v1.x, e1p); fma_f32x2(A3, v1.y, e1p);
#pragma unroll 4
            for (int e = 0; e < deg; e++) {
                int s    = __shfl_sync(FULL, s_l, e);
                float f0 = __shfl_sync(FULL, f0_l, e);
                float f1 = __shfl_sync(FULL, f1_l, e);
                ull f0p = pack2(f0), f1p = pack2(f1);
                const ulonglong2* xs = (const ulonglong2*)(xl + (size_t)s * FT);
                ulonglong2 u0 = xs[lane], u1 = xs[lane + 32];
                fma_f32x2(A0, u0.x, f0p); fma_f32x2(A1, u0.y, f0p);
                fma_f32x2(A2, u1.x, f1p); fma_f32x2(A3, u1.y, f1p);
            }
        }
    } else {
        float m0 = aself0, m1 = aself1;
        for (int i = beg + lane; i < end; i += 32) {
            int s = g_col[i];
            m0 = fmaxf(m0, leaky(g_asrc[2 * s]     + ad0));
            m1 = fmaxf(m1, leaky(g_asrc[2 * s + 1] + ad1));
        }
#pragma unroll
        for (int o = 16; o > 0; o >>= 1) {
            m0 = fmaxf(m0, __shfl_xor_sync(FULL, m0, o));
            m1 = fmaxf(m1, __shfl_xor_sync(FULL, m1, o));
        }
        float e0 = __expf(aself0 - m0), e1 = __expf(aself1 - m1);
        float dp0 = 0.f, dp1 = 0.f;

        if constexpr (F == 64) {
            ull ep = pack2((lane < 16) ? e0 : e1);
            ulonglong2 v = xrow[lane];
            fma_f32x2(A0, v.x, ep);
            fma_f32x2(A1, v.y, ep);
        } else {
            ull e0p = pack2(e0), e1p = pack2(e1);
            ulonglong2 v0 = xrow[lane], v1 = xrow[lane + 32];
            fma_f32x2(A0, v0.x, e0p); fma_f32x2(A1, v0.y, e0p);
            fma_f32x2(A2, v1.x, e1p); fma_f32x2(A3, v1.y, e1p);
        }

        for (int base = beg; base < end; base += 32) {
            int i = base + lane;
            bool vld = (i < end);
            int s_l = vld ? g_col[i] : 0;
            float f0_l = 0.f, f1_l = 0.f;
            if (vld) {
                f0_l = __expf(leaky(g_asrc[2 * s_l]     + ad0) - m0);
                f1_l = __expf(leaky(g_asrc[2 * s_l + 1] + ad1) - m1);
            }
            dp0 += f0_l; dp1 += f1_l;
            int cnt = min(32, end - base);
#pragma unroll 4
            for (int e = 0; e < cnt; e++) {
                int s    = __shfl_sync(FULL, s_l, e);
                float f0 = __shfl_sync(FULL, f0_l, e);
                float f1 = __shfl_sync(FULL, f1_l, e);
                if constexpr (F == 64) {
                    ull fp = pack2((lane < 16) ? f0 : f1);
                    ulonglong2 u = ((const ulonglong2*)(xl + (size_t)s * FT))[lane];
                    fma_f32x2(A0, u.x, fp);
                    fma_f32x2(A1, u.y, fp);
                } else {
                    ull f0p = pack2(f0), f1p = pack2(f1);
                    const ulonglong2* xs = (const ulonglong2*)(xl + (size_t)s * FT);
                    ulonglong2 u0 = xs[lane], u1 = xs[lane + 32];
                    fma_f32x2(A0, u0.x, f0p); fma_f32x2(A1, u0.y, f0p);
                    fma_f32x2(A2, u1.x, f1p); fma_f32x2(A3, u1.y, f1p);
                }
            }
        }
#pragma unroll
        for (int o = 16; o > 0; o >>= 1) {
            dp0 += __shfl_xor_sync(FULL, dp0, o);
            dp1 += __shfl_xor_sync(FULL, dp1, o);
        }
        den0 = dp0 + e0; den1 = dp1 + e1;
    }

    // epilogue: divide + bias
    const float4* b4 = (const float4*)bias;
    float4* orow = (float4*)(out + (size_t)w * FT);
    if constexpr (F == 64) {
        float id = 1.f / ((lane < 16) ? den0 : den1);
        float2 p0 = unpack2(A0), p1 = unpack2(A1);
        float4 bb = b4[lane];
        orow[lane] = make_float4(p0.x * id + bb.x, p0.y * id + bb.y,
                                 p1.x * id + bb.z, p1.y * id + bb.w);
    } else {
        float id0 = 1.f / den0, id1 = 1.f / den1;
        float2 p0 = unpack2(A0), p1 = unpack2(A1);
        float2 p2 = unpack2(A2), p3 = unpack2(A3);
        float4 b0 = b4[lane], b1 = b4[lane + 32];
        orow[lane]      = make_float4(p0.x * id0 + b0.x, p0.y * id0 + b0.y,
                                      p1.x * id0 + b0.z, p1.y * id0 + b0.w);
        orow[lane + 32] = make_float4(p2.x * id1 + b1.x, p2.y * id1 + b1.y,
                                      p3.x * id1 + b1.z, p3.y * id1 + b1.w);
    }
}

// ---------------------------------------------------------------------------

extern "C" void kernel_launch(void* const* d_in, const int* in_sizes, int n_in,
                              void* d_out, int out_size)
{
    const float* x   = (const float*)d_in[0];
    const int*   und = (const int*)d_in[1];
    const int*   dir = (const int*)d_in[2];
    const float* W1  = (const float*)d_in[3];
    const float* as1 = (const float*)d_in[4];
    const float* ad1 = (const float*)d_in[5];
    const float* b1  = (const float*)d_in[6];
    const float* W2  = (const float*)d_in[7];
    const float* as2 = (const float*)d_in[8];
    const float* ad2 = (const float*)d_in[9];
    const float* b2  = (const float*)d_in[10];
    float* out = (float*)d_out;

    const int n  = in_sizes[0] / 64;   // 50000
    const int e1 = in_sizes[1] / 2;    // 800000
    const int e2 = in_sizes[2] / 2;    // 800000

    float *xl1p, *out1p, *xl2p;
    cudaGetSymbolAddress((void**)&xl1p,  g_xl1);
    cudaGetSymbolAddress((void**)&out1p, g_out1);
    cudaGetSymbolAddress((void**)&xl2p,  g_xl2);

    const int T = 256;
    auto cdiv = [](long long a, long long b) { return (int)((a + b - 1) / b); };
    const int nsb = cdiv(n, 4096);

    // ---------------- Layer 1 (F=64, FT=128) ----------------
    gemm_kernel<64, 128><<<cdiv(n, 64), T>>>(x, W1, as1, ad1, xl1p, n);
    hist_kernel<<<cdiv(e1, T), T>>>(und + e1, e1);
    scanA_kernel<<<nsb, 1024>>>(n);
    scanB_kernel<<<1, 32>>>(nsb, n);
    scanC_kernel<<<cdiv(n, T), T>>>(n);
    scatter_kernel<<<cdiv(e1, T), T>>>(und, und + e1, e1);
    node_kernel<64><<<cdiv((long long)n * 32, T), T>>>(xl1p, b1, out1p, n);

    // ---------------- Layer 2 (F=128, FT=256) ----------------
    gemm_kernel<128, 256><<<cdiv(n, 64), T>>>(out1p, W2, as2, ad2, xl2p, n);
    hist_kernel<<<cdiv(e2, T), T>>>(dir + e2, e2);
    scanA_kernel<<<nsb, 1024>>>(n);
    scanB_kernel<<<1, 32>>>(nsb, n);
    scanC_kernel<<<cdiv(n, T), T>>>(n);
    scatter_kernel<<<cdiv(e2, T), T>>>(dir, dir + e2, e2);
    node_kernel<128><<<cdiv((long long)n * 32, T), T>>>(xl2p, b2, out, n);
}

// round 15
// speedup vs baseline: 1.3773x; 1.0451x over previous
#include <cuda_runtime.h>
#include <cstdint>

// ---------------------------------------------------------------------------
// 2-layer GAT (heads=2), CSR-based. FFMA2 GEMM with fused attention epilogue,
// packed-f32x2 node softmax-aggregate. CSR builds (per-layer buffers) run on
// forked side streams, overlapping the GEMM/node chain in the captured graph.
// ---------------------------------------------------------------------------

#define NN 50000
#define NE 800000

typedef unsigned long long ull;

__device__ float g_xl1[NN * 128];
__device__ float g_out1[NN * 128];
__device__ float g_xl2[NN * 256];
__device__ float g_asrc[NN * 2];
__device__ float g_adst[NN * 2];

// per-layer CSR buffers (cnt must be zero at entry; scanC re-zeroes)
__device__ int g_cnt1[NN],  g_cnt2[NN];
__device__ int g_rowptr1[NN + 1], g_rowptr2[NN + 1];
__device__ int g_off1[NN],  g_off2[NN];
__device__ int g_col1[NE],  g_col2[NE];
__device__ int g_bsum1[32], g_bsum2[32];

__device__ __forceinline__ float leaky(float a) { return a > 0.f ? a : 0.2f * a; }

__device__ __forceinline__ void fma_f32x2(ull& c, ull a, ull b) {
    asm("fma.rn.f32x2 %0, %1, %2, %0;" : "+l"(c) : "l"(a), "l"(b));
}
__device__ __forceinline__ float2 unpack2(ull v) {
    float lo, hi;
    asm("mov.b64 {%0,%1}, %2;" : "=f"(lo), "=f"(hi) : "l"(v));
    return make_float2(lo, hi);
}
__device__ __forceinline__ ull pack2(float f) {
    ull r;
    asm("mov.b64 %0, {%1,%1};" : "=l"(r) : "f"(f));
    return r;
}

// ---------------------------------------------------------------------------
// Packed GEMM + fused attention epilogue.
// ---------------------------------------------------------------------------
template <int KTOT, int NC>
__global__ __launch_bounds__(256)
void gemm_kernel(const float* __restrict__ A, const float* __restrict__ B,
                 const float* __restrict__ att_s, const float* __restrict__ att_d,
                 float* __restrict__ C, int M)
{
    constexpr int TM = 64, BK = 32;
    constexpr int RM = 8;
    constexpr int RN2 = NC / 64;
    const unsigned FULL = 0xffffffffu;

    __shared__ float2 sA2[BK][TM + 1];
    __shared__ float  sB[BK][NC];

    const int tid = threadIdx.x;
    const int tx = tid & 31, ty = tid >> 5;
    const int m0 = blockIdx.x * TM;

    ull acc2[RM][RN2];
#pragma unroll
    for (int i = 0; i < RM; i++)
#pragma unroll
        for (int j = 0; j < RN2; j++) acc2[i][j] = 0ull;

    for (int k0 = 0; k0 < KTOT; k0 += BK) {
#pragma unroll
        for (int i = 0; i < (TM * BK) / 256; i++) {
            int idx = tid + 256 * i;
            int r = idx >> 5;
            int kk = idx & 31;
            int row = m0 + r;
            float v = (row < M) ? A[(size_t)row * KTOT + k0 + kk] : 0.f;
            sA2[kk][r] = make_float2(v, v);
        }
#pragma unroll
        for (int i = 0; i < (BK * NC) / 256; i++) {
            int idx = tid + 256 * i;
            int kk = idx / NC;
            int c  = idx % NC;
            sB[kk][c] = B[(size_t)(k0 + kk) * NC + c];
        }
        __syncthreads();

#pragma unroll 4
        for (int kk = 0; kk < BK; kk++) {
            ull xv[RM], wv[RN2];
#pragma unroll
            for (int i = 0; i < RM; i++)
                xv[i] = *(const ull*)&sA2[kk][ty * RM + i];
#pragma unroll
            for (int j = 0; j < RN2; j++)
                wv[j] = *(const ull*)&sB[kk][64 * j + 2 * tx];
#pragma unroll
            for (int i = 0; i < RM; i++)
#pragma unroll
                for (int j = 0; j < RN2; j++)
                    fma_f32x2(acc2[i][j], xv[i], wv[j]);
        }
        __syncthreads();
    }

    float2 asv[RN2], adv[RN2];
#pragma unroll
    for (int j = 0; j < RN2; j++) {
        asv[j] = *(const float2*)&att_s[64 * j + 2 * tx];
        adv[j] = *(const float2*)&att_d[64 * j + 2 * tx];
    }
#pragma unroll
    for (int i = 0; i < RM; i++) {
        int row = m0 + ty * RM + i;
        if (row >= M) continue;
        float s0 = 0.f, s1 = 0.f, d0 = 0.f, d1 = 0.f;
#pragma unroll
        for (int j = 0; j < RN2; j++) {
            float2 c = unpack2(acc2[i][j]);
            *(float2*)&C[(size_t)row * NC + 64 * j + 2 * tx] = c;
            float ps = c.x * asv[j].x + c.y * asv[j].y;
            float pd = c.x * adv[j].x + c.y * adv[j].y;
            if (j < RN2 / 2) { s0 += ps; d0 += pd; }
            else             { s1 += ps; d1 += pd; }
        }
#pragma unroll
        for (int o = 16; o > 0; o >>= 1) {
            s0 += __shfl_xor_sync(FULL, s0, o);
            s1 += __shfl_xor_sync(FULL, s1, o);
            d0 += __shfl_xor_sync(FULL, d0, o);
            d1 += __shfl_xor_sync(FULL, d1, o);
        }
        if (tx == 0) {
            g_asrc[2 * row] = s0; g_asrc[2 * row + 1] = s1;
            g_adst[2 * row] = d0; g_adst[2 * row + 1] = d1;
        }
    }
}

// ---------------------------------------------------------------------------
// CSR construction (pointer-parameterized; cnt pre-zeroed, re-zeroed by scanC).
// ---------------------------------------------------------------------------
__global__ void hist_kernel(const int* __restrict__ dst, int* __restrict__ cnt, int ne)
{
    int i = blockIdx.x * blockDim.x + threadIdx.x;
    if (i < ne) atomicAdd(&cnt[dst[i]], 1);
}

__global__ __launch_bounds__(1024)
void scanA_kernel(const int* __restrict__ cnt, int* __restrict__ rowptr,
                  int* __restrict__ bsum, int n)
{
    __shared__ int wsum[32];
    int tid = threadIdx.x, lane = tid & 31, wid = tid >> 5;
    int i0 = blockIdx.x * 4096 + tid * 4;

    int c0 = 0, c1 = 0, c2 = 0, c3 = 0;
    if (i0 + 3 < n) {
        int4 t = *(const int4*)&cnt[i0];
        c0 = t.x; c1 = t.y; c2 = t.z; c3 = t.w;
    } else {
        if (i0     < n) c0 = cnt[i0];
        if (i0 + 1 < n) c1 = cnt[i0 + 1];
        if (i0 + 2 < n) c2 = cnt[i0 + 2];
        if (i0 + 3 < n) c3 = cnt[i0 + 3];
    }
    int v = c0 + c1 + c2 + c3;
    int s = v;
#pragma unroll
    for (int o = 1; o < 32; o <<= 1) {
        int t = __shfl_up_sync(0xffffffffu, s, o);
        if (lane >= o) s += t;
    }
    if (lane == 31) wsum[wid] = s;
    __syncthreads();
    if (wid == 0) {
        int ws = wsum[lane];
#pragma unroll
        for (int o = 1; o < 32; o <<= 1) {
            int t = __shfl_up_sync(0xffffffffu, ws, o);
            if (lane >= o) ws += t;
        }
        wsum[lane] = ws;
    }
    __syncthreads();
    int excl = s - v + (wid ? wsum[wid - 1] : 0);
    int e0 = excl, e1 = e0 + c0, e2 = e1 + c1, e3 = e2 + c2;
    if (i0     < n) rowptr[i0]     = e0;
    if (i0 + 1 < n) rowptr[i0 + 1] = e1;
    if (i0 + 2 < n) rowptr[i0 + 2] = e2;
    if (i0 + 3 < n) rowptr[i0 + 3] = e3;
    if (tid == 0) bsum[blockIdx.x] = wsum[31];
}

// scanC with fused scanB: warp 0 of every block redundantly scans bsum[0..nsb).
__global__ __launch_bounds__(256)
void scanC_kernel(int* __restrict__ rowptr, int* __restrict__ off,
                  int* __restrict__ cnt, const int* __restrict__ bsum,
                  int nsb, int n)
{
    __shared__ int sb[32];
    int tid = threadIdx.x;
    if (tid < 32) {
        int v = (tid < nsb) ? bsum[tid] : 0;
        int s = v;
#pragma unroll
        for (int o = 1; o < 32; o <<= 1) {
            int t = __shfl_up_sync(0xffffffffu, s, o);
            if (tid >= o) s += t;
        }
        sb[tid] = s - v;                          // exclusive
        if (blockIdx.x == 0 && tid == 31) rowptr[n] = s;
    }
    __syncthreads();
    int i = blockIdx.x * blockDim.x + tid;
    if (i >= n) return;
    int v = rowptr[i] + sb[i >> 12];
    rowptr[i] = v;
    off[i] = v;
    cnt[i] = 0;
}

__global__ void scatter_kernel(const int* __restrict__ src, const int* __restrict__ dst,
                               int* __restrict__ off, int* __restrict__ col, int ne)
{
    int i = blockIdx.x * blockDim.x + threadIdx.x;
    if (i >= ne) return;
    int pos = atomicAdd(&off[dst[i]], 1);
    col[pos] = src[i];
}

// ---------------------------------------------------------------------------
// Node kernel: warp per destination, chunked lane-parallel weights, shfl
// broadcast, packed-f32x2 accumulation.
// ---------------------------------------------------------------------------
template <int F>
__global__ __launch_bounds__(256)
void node_kernel(const float* __restrict__ xl, const float* __restrict__ bias,
                 const int* __restrict__ rowptr, const int* __restrict__ col,
                 float* __restrict__ out, int n_nodes)
{
    constexpr int FT = 2 * F;
    const unsigned FULL = 0xffffffffu;
    int w = (blockIdx.x * blockDim.x + threadIdx.x) >> 5;
    int lane = threadIdx.x & 31;
    if (w >= n_nodes) return;

    const int beg = rowptr[w], end = rowptr[w + 1];
    const int deg = end - beg;
    const float ad0 = g_adst[2 * w], ad1 = g_adst[2 * w + 1];
    const float aself0 = leaky(g_asrc[2 * w] + ad0);
    const float aself1 = leaky(g_asrc[2 * w + 1] + ad1);

    ull A0 = 0ull, A1 = 0ull, A2 = 0ull, A3 = 0ull;
    const ulonglong2* xrow = (const ulonglong2*)(xl + (size_t)w * FT);
    float den0, den1;

    if (deg <= 32) {
        int i = beg + lane;
        bool vld = (i < end);
        int s_l = vld ? col[i] : 0;
        float al0 = -1e30f, al1 = -1e30f;
        if (vld) {
            al0 = leaky(g_asrc[2 * s_l]     + ad0);
            al1 = leaky(g_asrc[2 * s_l + 1] + ad1);
        }
        float m0 = fmaxf(al0, aself0), m1 = fmaxf(al1, aself1);
#pragma unroll
        for (int o = 16; o > 0; o >>= 1) {
            m0 = fmaxf(m0, __shfl_xor_sync(FULL, m0, o));
            m1 = fmaxf(m1, __shfl_xor_sync(FULL, m1, o));
        }
        float f0_l = vld ? __expf(al0 - m0) : 0.f;
        float f1_l = vld ? __expf(al1 - m1) : 0.f;
        float d0 = f0_l, d1 = f1_l;
#pragma unroll
        for (int o = 16; o > 0; o >>= 1) {
            d0 += __shfl_xor_sync(FULL, d0, o);
            d1 += __shfl_xor_sync(FULL, d1, o);
        }
        float e0 = __expf(aself0 - m0), e1 = __expf(aself1 - m1);
        den0 = d0 + e0; den1 = d1 + e1;

        if constexpr (F == 64) {
            ull ep = pack2((lane < 16) ? e0 : e1);
            ulonglong2 v = xrow[lane];
            fma_f32x2(A0, v.x, ep);
            fma_f32x2(A1, v.y, ep);
#pragma unroll 4
            for (int e = 0; e < deg; e++) {
                int s    = __shfl_sync(FULL, s_l, e);
                float f0 = __shfl_sync(FULL, f0_l, e);
                float f1 = __shfl_sync(FULL, f1_l, e);
                ull fp = pack2((lane < 16) ? f0 : f1);
                ulonglong2 u = ((const ulonglong2*)(xl + (size_t)s * FT))[lane];
                fma_f32x2(A0, u.x, fp);
                fma_f32x2(A1, u.y, fp);
            }
        } else {
            ull e0p = pack2(e0), e1p = pack2(e1);
            ulonglong2 v0 = xrow[lane], v1 = xrow[lane + 32];
            fma_f32x2(A0, v0.x, e0p); fma_f32x2(A1, v0.y, e0p);
            fma_f32x2(A2, v1.x, e1p); fma_f32x2(A3, v1.y, e1p);
#pragma unroll 4
            for (int e = 0; e < deg; e++) {
                int s    = __shfl_sync(FULL, s_l, e);
                float f0 = __shfl_sync(FULL, f0_l, e);
                float f1 = __shfl_sync(FULL, f1_l, e);
                ull f0p = pack2(f0), f1p = pack2(f1);
                const ulonglong2* xs = (const ulonglong2*)(xl + (size_t)s * FT);
                ulonglong2 u0 = xs[lane], u1 = xs[lane + 32];
                fma_f32x2(A0, u0.x, f0p); fma_f32x2(A1, u0.y, f0p);
                fma_f32x2(A2, u1.x, f1p); fma_f32x2(A3, u1.y, f1p);
            }
        }
    } else {
        float m0 = aself0, m1 = aself1;
        for (int i = beg + lane; i < end; i += 32) {
            int s = col[i];
            m0 = fmaxf(m0, leaky(g_asrc[2 * s]     + ad0));
            m1 = fmaxf(m1, leaky(g_asrc[2 * s + 1] + ad1));
        }
#pragma unroll
        for (int o = 16; o > 0; o >>= 1) {
            m0 = fmaxf(m0, __shfl_xor_sync(FULL, m0, o));
            m1 = fmaxf(m1, __shfl_xor_sync(FULL, m1, o));
        }
        float e0 = __expf(aself0 - m0), e1 = __expf(aself1 - m1);
        float dp0 = 0.f, dp1 = 0.f;

        if constexpr (F == 64) {
            ull ep = pack2((lane < 16) ? e0 : e1);
            ulonglong2 v = xrow[lane];
            fma_f32x2(A0, v.x, ep);
            fma_f32x2(A1, v.y, ep);
        } else {
            ull e0p = pack2(e0), e1p = pack2(e1);
            ulonglong2 v0 = xrow[lane], v1 = xrow[lane + 32];
            fma_f32x2(A0, v0.x, e0p); fma_f32x2(A1, v0.y, e0p);
            fma_f32x2(A2, v1.x, e1p); fma_f32x2(A3, v1.y, e1p);
        }

        for (int base = beg; base < end; base += 32) {
            int i = base + lane;
            bool vld = (i < end);
            int s_l = vld ? col[i] : 0;
            float f0_l = 0.f, f1_l = 0.f;
            if (vld) {
                f0_l = __expf(leaky(g_asrc[2 * s_l]     + ad0) - m0);
                f1_l = __expf(leaky(g_asrc[2 * s_l + 1] + ad1) - m1);
            }
            dp0 += f0_l; dp1 += f1_l;
            int cnt = min(32, end - base);
#pragma unroll 4
            for (int e = 0; e < cnt; e++) {
                int s    = __shfl_sync(FULL, s_l, e);
                float f0 = __shfl_sync(FULL, f0_l, e);
                float f1 = __shfl_sync(FULL, f1_l, e);
                if constexpr (F == 64) {
                    ull fp = pack2((lane < 16) ? f0 : f1);
                    ulonglong2 u = ((const ulonglong2*)(xl + (size_t)s * FT))[lane];
                    fma_f32x2(A0, u.x, fp);
                    fma_f32x2(A1, u.y, fp);
                } else {
                    ull f0p = pack2(f0), f1p = pack2(f1);
                    const ulonglong2* xs = (const ulonglong2*)(xl + (size_t)s * FT);
                    ulonglong2 u0 = xs[lane], u1 = xs[lane + 32];
                    fma_f32x2(A0, u0.x, f0p); fma_f32x2(A1, u0.y, f0p);
                    fma_f32x2(A2, u1.x, f1p); fma_f32x2(A3, u1.y, f1p);
                }
            }
        }
#pragma unroll
        for (int o = 16; o > 0; o >>= 1) {
            dp0 += __shfl_xor_sync(FULL, dp0, o);
            dp1 += __shfl_xor_sync(FULL, dp1, o);
        }
        den0 = dp0 + e0; den1 = dp1 + e1;
    }

    const float4* b4 = (const float4*)bias;
    float4* orow = (float4*)(out + (size_t)w * FT);
    if constexpr (F == 64) {
        float id = 1.f / ((lane < 16) ? den0 : den1);
        float2 p0 = unpack2(A0), p1 = unpack2(A1);
        float4 bb = b4[lane];
        orow[lane] = make_float4(p0.x * id + bb.x, p0.y * id + bb.y,
                                 p1.x * id + bb.z, p1.y * id + bb.w);
    } else {
        float id0 = 1.f / den0, id1 = 1.f / den1;
        float2 p0 = unpack2(A0), p1 = unpack2(A1);
        float2 p2 = unpack2(A2), p3 = unpack2(A3);
        float4 b0 = b4[lane], b1 = b4[lane + 32];
        orow[lane]      = make_float4(p0.x * id0 + b0.x, p0.y * id0 + b0.y,
                                      p1.x * id0 + b0.z, p1.y * id0 + b0.w);
        orow[lane + 32] = make_float4(p2.x * id1 + b1.x, p2.y * id1 + b1.y,
                                      p3.x * id1 + b1.z, p3.y * id1 + b1.w);
    }
}

// ---------------------------------------------------------------------------

extern "C" void kernel_launch(void* const* d_in, const int* in_sizes, int n_in,
                              void* d_out, int out_size)
{
    const float* x   = (const float*)d_in[0];
    const int*   und = (const int*)d_in[1];
    const int*   dir = (const int*)d_in[2];
    const float* W1  = (const float*)d_in[3];
    const float* as1 = (const float*)d_in[4];
    const float* ad1 = (const float*)d_in[5];
    const float* b1  = (const float*)d_in[6];
    const float* W2  = (const float*)d_in[7];
    const float* as2 = (const float*)d_in[8];
    const float* ad2 = (const float*)d_in[9];
    const float* b2  = (const float*)d_in[10];
    float* out = (float*)d_out;

    const int n  = in_sizes[0] / 64;   // 50000
    const int e1 = in_sizes[1] / 2;    // 800000
    const int e2 = in_sizes[2] / 2;    // 800000

    float *xl1p, *out1p, *xl2p;
    int *cnt1, *cnt2, *rp1, *rp2, *off1, *off2, *col1, *col2, *bs1, *bs2;
    cudaGetSymbolAddress((void**)&xl1p,  g_xl1);
    cudaGetSymbolAddress((void**)&out1p, g_out1);
    cudaGetSymbolAddress((void**)&xl2p,  g_xl2);
    cudaGetSymbolAddress((void**)&cnt1, g_cnt1);
    cudaGetSymbolAddress((void**)&cnt2, g_cnt2);
    cudaGetSymbolAddress((void**)&rp1,  g_rowptr1);
    cudaGetSymbolAddress((void**)&rp2,  g_rowptr2);
    cudaGetSymbolAddress((void**)&off1, g_off1);
    cudaGetSymbolAddress((void**)&off2, g_off2);
    cudaGetSymbolAddress((void**)&col1, g_col1);
    cudaGetSymbolAddress((void**)&col2, g_col2);
    cudaGetSymbolAddress((void**)&bs1,  g_bsum1);
    cudaGetSymbolAddress((void**)&bs2,  g_bsum2);

    const int T = 256;
    auto cdiv = [](long long a, long long b) { return (int)((a + b - 1) / b); };
    const int nsb = cdiv(n, 4096);

    // persistent side streams + events (created once; host handles only)
    static cudaStream_t sA = nullptr, sB = nullptr;
    static cudaEvent_t evRoot = nullptr, evA = nullptr, evB = nullptr;
    if (!sA) {
        cudaStreamCreateWithFlags(&sA, cudaStreamNonBlocking);
        cudaStreamCreateWithFlags(&sB, cudaStreamNonBlocking);
        cudaEventCreateWithFlags(&evRoot, cudaEventDisableTiming);
        cudaEventCreateWithFlags(&evA, cudaEventDisableTiming);
        cudaEventCreateWithFlags(&evB, cudaEventDisableTiming);
    }

    // fork both CSR builds off the main (legacy) stream
    cudaEventRecord(evRoot, 0);
    cudaStreamWaitEvent(sA, evRoot, 0);
    cudaStreamWaitEvent(sB, evRoot, 0);

    // stream A: layer-1 CSR
    hist_kernel<<<cdiv(e1, T), T, 0, sA>>>(und + e1, cnt1, e1);
    scanA_kernel<<<nsb, 1024, 0, sA>>>(cnt1, rp1, bs1, n);
    scanC_kernel<<<cdiv(n, T), T, 0, sA>>>(rp1, off1, cnt1, bs1, nsb, n);
    scatter_kernel<<<cdiv(e1, T), T, 0, sA>>>(und, und + e1, off1, col1, e1);
    cudaEventRecord(evA, sA);

    // stream B: layer-2 CSR
    hist_kernel<<<cdiv(e2, T), T, 0, sB>>>(dir + e2, cnt2, e2);
    scanA_kernel<<<nsb, 1024, 0, sB>>>(cnt2, rp2, bs2, n);
    scanC_kernel<<<cdiv(n, T), T, 0, sB>>>(rp2, off2, cnt2, bs2, nsb, n);
    scatter_kernel<<<cdiv(e2, T), T, 0, sB>>>(dir, dir + e2, off2, col2, e2);
    cudaEventRecord(evB, sB);

    // main chain
    gemm_kernel<64, 128><<<cdiv(n, 64), T>>>(x, W1, as1, ad1, xl1p, n);
    cudaStreamWaitEvent(0, evA, 0);
    node_kernel<64><<<cdiv((long long)n * 32, T), T>>>(xl1p, b1, rp1, col1, out1p, n);

    gemm_kernel<128, 256><<<cdiv(n, 64), T>>>(out1p, W2, as2, ad2, xl2p, n);
    cudaStreamWaitEvent(0, evB, 0);
    node_kernel<128><<<cdiv((long long)n * 32, T), T>>>(xl2p, b2, rp2, col2, out, n);
}